// round 13
// baseline (speedup 1.0000x reference)
#include <cuda_runtime.h>
#include <cuda_bf16.h>
#include <math.h>
#include <float.h>
#include <stdint.h>

#define BATCH 2048
#define SEQ   32
#define DIM   1024
#define HID   1024
#define MS    4096
#define NK    32

typedef __nv_bfloat16 bf16;

// Tiled layout: tile = 128 rows x 64 cols bf16 = 16KB, SW128-swizzled.
#define TILE_E 8192
#define TILE_B 16384

// ------------------------------- scratch -----------------------------------
__device__ bf16 g_x3[(size_t)BATCH * SEQ * 2 * DIM];
__device__ bf16 g_We3[(size_t)HID * 2 * DIM];
__device__ bf16 g_mem3[(size_t)MS * 2 * HID];
__device__ bf16 g_as[(size_t)MS * MS];
__device__ bf16 g_Wd3[(size_t)DIM * 2 * HID];
__device__ bf16 g_q3[(size_t)BATCH * 2 * HID];
__device__ bf16 g_act[(size_t)BATCH * MS];
__device__ bf16 g_read3[(size_t)BATCH * 2 * HID];
__device__ float g_query[(size_t)BATCH * HID];
__device__ float g_sim[(size_t)BATCH * MS];
__device__ float g_actB[(size_t)BATCH * MS];
__device__ float g_orow[(size_t)BATCH * DIM];
__device__ float g_vals[BATCH * NK];
__device__ int   g_idx[BATCH * NK];

// ------------------------------ helpers ------------------------------------
__device__ __forceinline__ uint32_t s2u(const void* p) {
    uint32_t a;
    asm("{ .reg .u64 t; cvta.to.shared.u64 t, %1; cvt.u32.u64 %0, t; }" : "=r"(a) : "l"(p));
    return a;
}
__device__ __forceinline__ uint32_t swz(uint32_t lin) {
    return lin ^ ((lin >> 3) & 0x70u);
}
__device__ __forceinline__ void ldsm4(uint32_t* r, uint32_t a) {
    asm volatile("ldmatrix.sync.aligned.m8n8.x4.shared.b16 {%0,%1,%2,%3}, [%4];"
        : "=r"(r[0]), "=r"(r[1]), "=r"(r[2]), "=r"(r[3]) : "r"(a));
}
__device__ __forceinline__ void ldsm2(uint32_t* r, uint32_t a) {
    asm volatile("ldmatrix.sync.aligned.m8n8.x2.shared.b16 {%0,%1}, [%2];"
        : "=r"(r[0]), "=r"(r[1]) : "r"(a));
}
__device__ __forceinline__ void mma16816(float* c, const uint32_t* a, const uint32_t* b) {
    asm volatile("mma.sync.aligned.m16n8k16.row.col.f32.bf16.bf16.f32 "
        "{%0,%1,%2,%3}, {%4,%5,%6,%7}, {%8,%9}, {%0,%1,%2,%3};"
        : "+f"(c[0]), "+f"(c[1]), "+f"(c[2]), "+f"(c[3])
        : "r"(a[0]), "r"(a[1]), "r"(a[2]), "r"(a[3]), "r"(b[0]), "r"(b[1]));
}
__device__ __forceinline__ float fast_tanh(float x) {
    float ax = fabsf(x);
    float t = __expf(-2.0f * ax);
    float r = (1.0f - t) / (1.0f + t);
    return copysignf(r, x);
}
__device__ __forceinline__ uint32_t pk2(float a, float b) {
    __nv_bfloat162 h;
    h.x = __float2bfloat16(a); h.y = __float2bfloat16(b);
    return *(uint32_t*)&h;
}

#define MBARRIER_INIT(mb, c) \
    asm volatile("mbarrier.init.shared.b64 [%0], %1;" :: "r"((uint32_t)(mb)), "r"((uint32_t)(c)) : "memory")
#define MBAR_ARRIVE_EXPECT(mb, tx) \
    asm volatile("mbarrier.arrive.expect_tx.shared.b64 _, [%0], %1;" :: "r"((uint32_t)(mb)), "r"((uint32_t)(tx)) : "memory")
#define BULK_G2S(dst, src, bytes, mb) \
    asm volatile("cp.async.bulk.shared::cluster.global.mbarrier::complete_tx::bytes [%0], [%1], %2, [%3];" \
        :: "r"((uint32_t)(dst)), "l"(src), "r"((uint32_t)(bytes)), "r"((uint32_t)(mb)) : "memory")
#define MBARRIER_WAIT_PARITY(mb, ph) do {                                              \
    uint32_t _mb = (uint32_t)(mb); uint32_t _ph = (uint32_t)(ph); uint32_t _done;      \
    asm volatile("{\n .reg .pred p;\n"                                                 \
        " mbarrier.try_wait.parity.acquire.cta.shared::cta.b64 p, [%1], %2;\n"         \
        " selp.b32 %0, 1, 0, p;\n}"                                                    \
        : "=r"(_done) : "r"(_mb), "r"(_ph) : "memory");                                \
    if (!_done) {                                                                      \
        asm volatile("{\n .reg .pred P1;\n"                                            \
            "WL_%=:\n"                                                                 \
            " mbarrier.try_wait.parity.acquire.cta.shared::cta.b64 P1, [%0], %1, 0x989680;\n" \
            " @P1 bra.uni WD_%=;\n bra.uni WL_%=;\nWD_%=:\n}"                          \
            :: "r"(_mb), "r"(_ph) : "memory");                                         \
    }                                                                                  \
} while (0)

// ----------------------------- GEMM ----------------------------------------
// C[M,N] = A @ B^T, tiled-swizzled bf16 operands.
// BM=256, BN=128. 512 threads, 16 warps 4x4, warp tile 64x32.
// TERMS==3: BK=64 fat chunks {A hi,lo}x2 + {B hi,lo} (96KB), 3 passes, 2 stg.
// TERMS==1: BK=128 chunks {A}x2x2kb + {B}x2kb (96KB), 2 stages.
// EPI: 0 = fp32 C store; 1 = encoder tanh+bias+mean -> query/q3.
#define SMEM_BYTES (1024 + 196608)

template <int EPI, int TERMS>
__global__ void __launch_bounds__(512, 1)
k_gemm(const bf16* __restrict__ A, const bf16* __restrict__ B,
       int nkbA, int nkbB, int K,
       float* __restrict__ C, int Nst,
       const float* __restrict__ bias,
       float* __restrict__ qout, bf16* __restrict__ q3out)
{
    extern __shared__ char smem[];
    const uint32_t sb = s2u(smem);
    const int tid = threadIdx.x, wid = tid >> 5, lane = tid & 31;
    const int wr = wid >> 2, wc = wid & 3;
    const int m0 = blockIdx.y * 256, n0 = blockIdx.x * 128;
    const int Kb = K / 64;
    const int rbA0 = blockIdx.y * 2;
    const int nb = blockIdx.x;

    if (tid == 0) {
#pragma unroll
        for (int s = 0; s < 4; s++) MBARRIER_INIT(sb + s * 8, 1);
    }
    __syncthreads();

    const uint32_t aTileSel = (wr >= 2) ? (uint32_t)TILE_B : 0u;
    uint32_t alin[4], blin[4];
#pragma unroll
    for (int mi = 0; mi < 4; mi++)
        alin[mi] = (uint32_t)(((wr & 1) * 64) + mi * 16 + (lane & 15)) * 128u + (uint32_t)(lane >> 4) * 16u;
#pragma unroll
    for (int ni = 0; ni < 4; ni++)
        blin[ni] = (uint32_t)(wc * 32 + ni * 8 + (lane & 7)) * 128u + (uint32_t)((lane >> 3) & 1) * 16u;

    float acc[4][4][4];
#pragma unroll
    for (int a = 0; a < 4; a++)
#pragma unroll
        for (int b = 0; b < 4; b++)
#pragma unroll
            for (int c = 0; c < 4; c++) acc[a][b][c] = 0.f;

    if (TERMS == 3) {
        const int NC = Kb;
        if (tid == 0) {
#pragma unroll
            for (int c0 = 0; c0 < 2; c0++) {
                if (c0 >= NC) break;
                uint32_t mb = sb + (uint32_t)c0 * 8;
                uint32_t dst = sb + 1024u + (uint32_t)c0 * 98304u;
                MBAR_ARRIVE_EXPECT(mb, 98304u);
                BULK_G2S(dst,           A + ((size_t)rbA0 * nkbA + c0) * TILE_E, TILE_B, mb);
                BULK_G2S(dst + 16384u,  A + ((size_t)(rbA0 + 1) * nkbA + c0) * TILE_E, TILE_B, mb);
                BULK_G2S(dst + 32768u,  A + ((size_t)rbA0 * nkbA + c0 + Kb) * TILE_E, TILE_B, mb);
                BULK_G2S(dst + 49152u,  A + ((size_t)(rbA0 + 1) * nkbA + c0 + Kb) * TILE_E, TILE_B, mb);
                BULK_G2S(dst + 65536u,  B + ((size_t)nb * nkbB + c0) * TILE_E, TILE_B, mb);
                BULK_G2S(dst + 81920u,  B + ((size_t)nb * nkbB + c0 + Kb) * TILE_E, TILE_B, mb);
            }
        }
        for (int c = 0; c < NC; c++) {
            int s = c & 1;
            MBARRIER_WAIT_PARITY(sb + s * 8, (c >> 1) & 1);
            const uint32_t stg = sb + 1024u + (uint32_t)s * 98304u;
            const uint32_t Ah = stg + aTileSel;
            const uint32_t Al = stg + 32768u + aTileSel;
            const uint32_t Bh = stg + 65536u;
            const uint32_t Bl = stg + 81920u;
#pragma unroll
            for (int ks = 0; ks < 4; ks++) {
                uint32_t af[4][4], bh[4][2], bl[4][2];
#pragma unroll
                for (int mi = 0; mi < 4; mi++) ldsm4(af[mi], Ah + swz(alin[mi] + ks * 32u));
#pragma unroll
                for (int ni = 0; ni < 4; ni++) ldsm2(bh[ni], Bh + swz(blin[ni] + ks * 32u));
#pragma unroll
                for (int ni = 0; ni < 4; ni++) ldsm2(bl[ni], Bl + swz(blin[ni] + ks * 32u));
#pragma unroll
                for (int mi = 0; mi < 4; mi++)
#pragma unroll
                    for (int ni = 0; ni < 4; ni++) mma16816(acc[mi][ni], af[mi], bh[ni]);
#pragma unroll
                for (int mi = 0; mi < 4; mi++)
#pragma unroll
                    for (int ni = 0; ni < 4; ni++) mma16816(acc[mi][ni], af[mi], bl[ni]);
#pragma unroll
                for (int mi = 0; mi < 4; mi++) ldsm4(af[mi], Al + swz(alin[mi] + ks * 32u));
#pragma unroll
                for (int mi = 0; mi < 4; mi++)
#pragma unroll
                    for (int ni = 0; ni < 4; ni++) mma16816(acc[mi][ni], af[mi], bh[ni]);
            }
            __syncthreads();
            if (c + 2 < NC && tid == 0) {
                int cn = c + 2;
                uint32_t mb = sb + (uint32_t)s * 8;
                uint32_t dst = sb + 1024u + (uint32_t)s * 98304u;
                MBAR_ARRIVE_EXPECT(mb, 98304u);
                BULK_G2S(dst,           A + ((size_t)rbA0 * nkbA + cn) * TILE_E, TILE_B, mb);
                BULK_G2S(dst + 16384u,  A + ((size_t)(rbA0 + 1) * nkbA + cn) * TILE_E, TILE_B, mb);
                BULK_G2S(dst + 32768u,  A + ((size_t)rbA0 * nkbA + cn + Kb) * TILE_E, TILE_B, mb);
                BULK_G2S(dst + 49152u,  A + ((size_t)(rbA0 + 1) * nkbA + cn + Kb) * TILE_E, TILE_B, mb);
                BULK_G2S(dst + 65536u,  B + ((size_t)nb * nkbB + cn) * TILE_E, TILE_B, mb);
                BULK_G2S(dst + 81920u,  B + ((size_t)nb * nkbB + cn + Kb) * TILE_E, TILE_B, mb);
            }
        }
    } else {
        // BK=128: chunk c covers kb = 2c, 2c+1. 96KB stage, 2 stages.
        // layout: A(rb0,kb0)@0  A(rb1,kb0)@16K  A(rb0,kb1)@32K  A(rb1,kb1)@48K
        //         B(kb0)@64K   B(kb1)@80K
        const int NC = Kb / 2;
        if (tid == 0) {
#pragma unroll
            for (int c0 = 0; c0 < 2; c0++) {
                if (c0 >= NC) break;
                int kb0 = 2 * c0;
                uint32_t mb = sb + (uint32_t)c0 * 8;
                uint32_t dst = sb + 1024u + (uint32_t)c0 * 98304u;
                MBAR_ARRIVE_EXPECT(mb, 98304u);
                BULK_G2S(dst,           A + ((size_t)rbA0 * nkbA + kb0) * TILE_E, TILE_B, mb);
                BULK_G2S(dst + 16384u,  A + ((size_t)(rbA0 + 1) * nkbA + kb0) * TILE_E, TILE_B, mb);
                BULK_G2S(dst + 32768u,  A + ((size_t)rbA0 * nkbA + kb0 + 1) * TILE_E, TILE_B, mb);
                BULK_G2S(dst + 49152u,  A + ((size_t)(rbA0 + 1) * nkbA + kb0 + 1) * TILE_E, TILE_B, mb);
                BULK_G2S(dst + 65536u,  B + ((size_t)nb * nkbB + kb0) * TILE_E, TILE_B, mb);
                BULK_G2S(dst + 81920u,  B + ((size_t)nb * nkbB + kb0 + 1) * TILE_E, TILE_B, mb);
            }
        }
        for (int c = 0; c < NC; c++) {
            int s = c & 1;
            MBARRIER_WAIT_PARITY(sb + s * 8, (c >> 1) & 1);
            const uint32_t stg = sb + 1024u + (uint32_t)s * 98304u;
#pragma unroll
            for (int h = 0; h < 2; h++) {
                const uint32_t As = stg + (uint32_t)h * 32768u + aTileSel;
                const uint32_t Bs = stg + 65536u + (uint32_t)h * 16384u;
#pragma unroll
                for (int ks = 0; ks < 4; ks++) {
                    uint32_t af[4][4], bfr[4][2];
#pragma unroll
                    for (int mi = 0; mi < 4; mi++) ldsm4(af[mi], As + swz(alin[mi] + ks * 32u));
#pragma unroll
                    for (int ni = 0; ni < 4; ni++) ldsm2(bfr[ni], Bs + swz(blin[ni] + ks * 32u));
#pragma unroll
                    for (int mi = 0; mi < 4; mi++)
#pragma unroll
                        for (int ni = 0; ni < 4; ni++) mma16816(acc[mi][ni], af[mi], bfr[ni]);
                }
            }
            __syncthreads();
            if (c + 2 < NC && tid == 0) {
                int kb0 = 2 * (c + 2);
                uint32_t mb = sb + (uint32_t)s * 8;
                uint32_t dst = sb + 1024u + (uint32_t)s * 98304u;
                MBAR_ARRIVE_EXPECT(mb, 98304u);
                BULK_G2S(dst,           A + ((size_t)rbA0 * nkbA + kb0) * TILE_E, TILE_B, mb);
                BULK_G2S(dst + 16384u,  A + ((size_t)(rbA0 + 1) * nkbA + kb0) * TILE_E, TILE_B, mb);
                BULK_G2S(dst + 32768u,  A + ((size_t)rbA0 * nkbA + kb0 + 1) * TILE_E, TILE_B, mb);
                BULK_G2S(dst + 49152u,  A + ((size_t)(rbA0 + 1) * nkbA + kb0 + 1) * TILE_E, TILE_B, mb);
                BULK_G2S(dst + 65536u,  B + ((size_t)nb * nkbB + kb0) * TILE_E, TILE_B, mb);
                BULK_G2S(dst + 81920u,  B + ((size_t)nb * nkbB + kb0 + 1) * TILE_E, TILE_B, mb);
            }
        }
    }

    if (EPI == 0) {
#pragma unroll
        for (int mi = 0; mi < 4; mi++) {
            int r = m0 + wr * 64 + mi * 16 + (lane >> 2);
#pragma unroll
            for (int ni = 0; ni < 4; ni++) {
                int col = n0 + wc * 32 + ni * 8 + 2 * (lane & 3);
                *(float2*)&C[(size_t)r * Nst + col] = make_float2(acc[mi][ni][0], acc[mi][ni][1]);
                *(float2*)&C[(size_t)(r + 8) * Nst + col] = make_float2(acc[mi][ni][2], acc[mi][ni][3]);
            }
        }
    } else {
        // rows = batch*SEQ; 32-row group = one batch; warp holds 2 batches.
#pragma unroll
        for (int b = 0; b < 2; b++) {
            int batch = m0 / 32 + wr * 2 + b;
#pragma unroll
            for (int ni = 0; ni < 4; ni++) {
                int col0 = n0 + wc * 32 + ni * 8 + 2 * (lane & 3);
                float bi0 = bias[col0], bi1 = bias[col0 + 1];
                float s0 = 0.f, s1 = 0.f;
#pragma unroll
                for (int mh = 0; mh < 2; mh++) {
                    float* cc = acc[b * 2 + mh][ni];
                    s0 += fast_tanh(cc[0] + bi0) + fast_tanh(cc[2] + bi0);
                    s1 += fast_tanh(cc[1] + bi1) + fast_tanh(cc[3] + bi1);
                }
#pragma unroll
                for (int o = 4; o <= 16; o <<= 1) {
                    s0 += __shfl_xor_sync(0xffffffffu, s0, o);
                    s1 += __shfl_xor_sync(0xffffffffu, s1, o);
                }
                if (lane < 4) {
                    float q0 = s0 * (1.0f / SEQ), q1 = s1 * (1.0f / SEQ);
                    qout[(size_t)batch * HID + col0] = q0;
                    qout[(size_t)batch * HID + col0 + 1] = q1;
                    uint32_t lin = swz(((uint32_t)(batch & 127) << 7) + ((uint32_t)(col0 & 63) << 1));
                    int rb = batch >> 7, kb = col0 >> 6;
                    char* th = (char*)q3out + ((size_t)rb * (2 * HID / 64) + kb) * TILE_B + lin;
                    char* tl = (char*)q3out + ((size_t)rb * (2 * HID / 64) + kb + HID / 64) * TILE_B + lin;
                    bf16 h0 = __float2bfloat16(q0), h1 = __float2bfloat16(q1);
                    *(uint32_t*)th = pk2(q0, q1);
                    *(uint32_t*)tl = pk2(q0 - __bfloat162float(h0), q1 - __bfloat162float(h1));
                }
            }
        }
    }
}

// ---------------------- prep: row-major fp32 -> tiled hi|lo ----------------
__global__ void k_dec_t(const float* __restrict__ in, bf16* __restrict__ out,
                        int K, long nGran)
{
    long g = (long)blockIdx.x * 256 + threadIdx.x;
    if (g >= nGran) return;
    int perRow = K / 8;
    long r = g / perRow;
    int c = (int)(g % perRow) * 8;
    float4 v0 = *(const float4*)(in + r * K + c);
    float4 v1 = *(const float4*)(in + r * K + c + 4);
    float f[8] = {v0.x, v0.y, v0.z, v0.w, v1.x, v1.y, v1.z, v1.w};
    uint32_t hi[4], lo[4];
#pragma unroll
    for (int j = 0; j < 4; j++) {
        bf16 h0 = __float2bfloat16(f[2 * j]), h1 = __float2bfloat16(f[2 * j + 1]);
        __nv_bfloat162 hp; hp.x = h0; hp.y = h1;
        hi[j] = *(uint32_t*)&hp;
        lo[j] = pk2(f[2 * j] - __bfloat162float(h0), f[2 * j + 1] - __bfloat162float(h1));
    }
    int rb = (int)(r >> 7), kb = c >> 6, kbT = 2 * K / 64;
    uint32_t lin = swz(((uint32_t)(r & 127) << 7) + ((uint32_t)(c & 63) << 1));
    *(uint4*)((char*)out + ((size_t)rb * kbT + kb) * TILE_B + lin) = make_uint4(hi[0], hi[1], hi[2], hi[3]);
    *(uint4*)((char*)out + ((size_t)rb * kbT + kb + K / 64) * TILE_B + lin) = make_uint4(lo[0], lo[1], lo[2], lo[3]);
}

// ------------- prep: transpose fp32 [K][N] -> tiled rows=n ------------------
template <bool LO>
__global__ void k_tdec_t(const float* __restrict__ in, bf16* __restrict__ out,
                         int K, int N)
{
    __shared__ float tile[32][33];
    int n0 = blockIdx.x * 32, k0 = blockIdx.y * 32;
    int tx = threadIdx.x & 31, ty = threadIdx.x >> 5;
    for (int r = ty; r < 32; r += 8)
        tile[r][tx] = in[(size_t)(k0 + r) * N + n0 + tx];
    __syncthreads();
    int t = threadIdx.x;
    if (t < 128) {
        int nl = t & 31, kg = t >> 5;
        float f[8];
#pragma unroll
        for (int j = 0; j < 8; j++) f[j] = tile[kg * 8 + j][nl];
        int n = n0 + nl, k = k0 + kg * 8;
        uint32_t hi[4], lo[4];
#pragma unroll
        for (int j = 0; j < 4; j++) {
            bf16 h0 = __float2bfloat16(f[2 * j]), h1 = __float2bfloat16(f[2 * j + 1]);
            __nv_bfloat162 hp; hp.x = h0; hp.y = h1;
            hi[j] = *(uint32_t*)&hp;
            if (LO)
                lo[j] = pk2(f[2 * j] - __bfloat162float(h0), f[2 * j + 1] - __bfloat162float(h1));
        }
        int rb = n >> 7, kb = k >> 6;
        int kbT = LO ? 2 * K / 64 : K / 64;
        uint32_t lin = swz(((uint32_t)(n & 127) << 7) + ((uint32_t)(k & 63) << 1));
        *(uint4*)((char*)out + ((size_t)rb * kbT + kb) * TILE_B + lin) = make_uint4(hi[0], hi[1], hi[2], hi[3]);
        if (LO)
            *(uint4*)((char*)out + ((size_t)rb * kbT + kb + K / 64) * TILE_B + lin) = make_uint4(lo[0], lo[1], lo[2], lo[3]);
    }
}

// ---- fused: gate + top-k + softmax over one sim row (block = one batch) ----
__global__ void k_simfuse(const float* __restrict__ sim,
                          const float* __restrict__ query,
                          const float* __restrict__ w_curv,
                          const float* __restrict__ b_curv,
                          const float* __restrict__ temperature,
                          bf16* __restrict__ out)
{
    __shared__ float sv[MS];
    __shared__ float red[256];
    __shared__ float cv[256];
    __shared__ int   ci[256];
    __shared__ float s_scale;

    int b = blockIdx.x, tid = threadIdx.x;
    int w = tid >> 5, lane = tid & 31;

    const float* row = sim + (size_t)b * MS;
    float mx = -FLT_MAX;
    for (int i = tid; i < MS; i += 256) { float v = row[i]; sv[i] = v; mx = fmaxf(mx, v); }

    float gs = 0.f;
    for (int h = tid; h < HID; h += 256)
        gs += query[(size_t)b * HID + h] * w_curv[h];
    red[tid] = gs; __syncthreads();
    for (int off = 128; off; off >>= 1) { if (tid < off) red[tid] += red[tid + off]; __syncthreads(); }
    if (tid == 0) {
        float gate = 1.0f / (1.0f + expf(-(red[0] + b_curv[0])));
        s_scale = (0.5f + gate) / fmaxf(temperature[0], 1e-6f);
    }
    __syncthreads();
    float scale = s_scale;

    red[tid] = mx; __syncthreads();
    for (int off = 128; off; off >>= 1) { if (tid < off) red[tid] = fmaxf(red[tid], red[tid + off]); __syncthreads(); }
    mx = red[0]; __syncthreads();

    float v[16];
#pragma unroll
    for (int j = 0; j < 16; j++) v[j] = sv[w * 512 + j * 32 + lane] * scale;

    for (int it = 0; it < NK; it++) {
        float bv = -FLT_MAX; int bj = 0;
#pragma unroll
        for (int j = 0; j < 16; j++)
            if (v[j] > bv) { bv = v[j]; bj = j; }
        int bi = w * 512 + bj * 32 + lane;
#pragma unroll
        for (int o = 16; o; o >>= 1) {
            float ov = __shfl_xor_sync(0xffffffffu, bv, o);
            int   oi = __shfl_xor_sync(0xffffffffu, bi, o);
            if (ov > bv || (ov == bv && oi < bi)) { bv = ov; bi = oi; }
        }
        if ((bi & 31) == lane) v[(bi >> 5) & 15] = -FLT_MAX;
        if (lane == 0) { cv[w * 32 + it] = bv; ci[w * 32 + it] = bi; }
    }
    __syncthreads();

    if (w == 0) {
        float pv[8]; int pi[8];
#pragma unroll
        for (int j = 0; j < 8; j++) { pv[j] = cv[lane + j * 32]; pi[j] = ci[lane + j * 32]; }
        for (int k = 0; k < NK; k++) {
            float bv = -FLT_MAX; int bi = 0x7FFFFFFF;
#pragma unroll
            for (int j = 0; j < 8; j++)
                if (pv[j] > bv || (pv[j] == bv && pi[j] < bi)) { bv = pv[j]; bi = pi[j]; }
#pragma unroll
            for (int o = 16; o; o >>= 1) {
                float ov = __shfl_xor_sync(0xffffffffu, bv, o);
                int   oi = __shfl_xor_sync(0xffffffffu, bi, o);
                if (ov > bv || (ov == bv && oi < bi)) { bv = ov; bi = oi; }
            }
#pragma unroll
            for (int j = 0; j < 8; j++)
                if (pi[j] == bi) pv[j] = -FLT_MAX;
            if (lane == 0) {
                g_vals[(size_t)b * NK + k] = bv;
                g_idx [(size_t)b * NK + k] = bi;
            }
        }
    }
    __syncthreads();

    float s = 0.f;
    for (int i = tid; i < MS; i += 256) { float e = expf(sv[i] - mx); sv[i] = e; s += e; }
    red[tid] = s; __syncthreads();
    for (int off = 128; off; off >>= 1) { if (tid < off) red[tid] += red[tid + off]; __syncthreads(); }
    float inv = 1.0f / red[0];
    int rb = b >> 7;
    uint32_t rlin = (uint32_t)(b & 127) << 7;
    for (int gI = tid; gI < MS / 8; gI += 256) {
        int c = gI * 8;
        uint32_t hi[4];
#pragma unroll
        for (int j = 0; j < 4; j++)
            hi[j] = pk2(sv[c + 2 * j] * inv, sv[c + 2 * j + 1] * inv);
        uint32_t lin = swz(rlin + ((uint32_t)(c & 63) << 1));
        *(uint4*)((char*)out + ((size_t)rb * (MS / 64) + (c >> 6)) * TILE_B + lin)
            = make_uint4(hi[0], hi[1], hi[2], hi[3]);
    }
}

// ------------- softmax over M=4096 -> tiled bf16 (hi only) ------------------
__global__ void k_softmax_dec(const float* __restrict__ in, bf16* __restrict__ out)
{
    __shared__ float sv[MS];
    __shared__ float red[256];
    int b = blockIdx.x, tid = threadIdx.x;
    const float* row = in + (size_t)b * MS;
    float mx = -FLT_MAX;
    for (int i = tid; i < MS; i += 256) { float v = row[i]; sv[i] = v; mx = fmaxf(mx, v); }
    red[tid] = mx; __syncthreads();
    for (int off = 128; off; off >>= 1) { if (tid < off) red[tid] = fmaxf(red[tid], red[tid + off]); __syncthreads(); }
    mx = red[0]; __syncthreads();
    float s = 0.f;
    for (int i = tid; i < MS; i += 256) { float e = expf(sv[i] - mx); sv[i] = e; s += e; }
    red[tid] = s; __syncthreads();
    for (int off = 128; off; off >>= 1) { if (tid < off) red[tid] += red[tid + off]; __syncthreads(); }
    float inv = 1.0f / red[0];
    int rb = b >> 7;
    uint32_t rlin = (uint32_t)(b & 127) << 7;
    for (int gI = tid; gI < MS / 8; gI += 256) {
        int c = gI * 8;
        uint32_t hi[4];
#pragma unroll
        for (int j = 0; j < 4; j++)
            hi[j] = pk2(sv[c + 2 * j] * inv, sv[c + 2 * j + 1] * inv);
        uint32_t lin = swz(rlin + ((uint32_t)(c & 63) << 1));
        *(uint4*)((char*)out + ((size_t)rb * (MS / 64) + (c >> 6)) * TILE_B + lin)
            = make_uint4(hi[0], hi[1], hi[2], hi[3]);
    }
}

// ------- combine: softmax(vals + act[idx]); read3 (tiled hi|lo) -------------
__global__ void k_combine(const float* __restrict__ act,
                          const float* __restrict__ mem)
{
    __shared__ float comb[NK];
    __shared__ int   sidx[NK];
    int b = blockIdx.x, tid = threadIdx.x;
    if (tid < NK) {
        int id = g_idx[(size_t)b * NK + tid];
        sidx[tid] = id;
        float t = g_vals[(size_t)b * NK + tid] + act[(size_t)b * MS + id];
        float m = t;
#pragma unroll
        for (int o = 16; o; o >>= 1) m = fmaxf(m, __shfl_xor_sync(0xffffffffu, m, o));
        float e = expf(t - m);
        float s = e;
#pragma unroll
        for (int o = 16; o; o >>= 1) s += __shfl_xor_sync(0xffffffffu, s, o);
        comb[tid] = e / s;
    }
    __syncthreads();
    int rb = b >> 7;
    uint32_t rlin = (uint32_t)(b & 127) << 7;
    if (tid < HID / 8) {
        int h0 = tid * 8;
        float a[8] = {0, 0, 0, 0, 0, 0, 0, 0};
#pragma unroll
        for (int k = 0; k < NK; k++) {
            float cb = comb[k];
            const float4* mr = (const float4*)(mem + (size_t)sidx[k] * HID + h0);
            float4 m0 = mr[0], m1 = mr[1];
            a[0] += cb * m0.x; a[1] += cb * m0.y; a[2] += cb * m0.z; a[3] += cb * m0.w;
            a[4] += cb * m1.x; a[5] += cb * m1.y; a[6] += cb * m1.z; a[7] += cb * m1.w;
        }
        uint32_t hi[4], lo[4];
#pragma unroll
        for (int j = 0; j < 4; j++) {
            bf16 h0b = __float2bfloat16(a[2 * j]), h1b = __float2bfloat16(a[2 * j + 1]);
            __nv_bfloat162 hp; hp.x = h0b; hp.y = h1b;
            hi[j] = *(uint32_t*)&hp;
            lo[j] = pk2(a[2 * j] - __bfloat162float(h0b), a[2 * j + 1] - __bfloat162float(h1b));
        }
        int kb = h0 >> 6;
        uint32_t lin = swz(rlin + ((uint32_t)(h0 & 63) << 1));
        *(uint4*)((char*)g_read3 + ((size_t)rb * (2 * HID / 64) + kb) * TILE_B + lin)
            = make_uint4(hi[0], hi[1], hi[2], hi[3]);
        *(uint4*)((char*)g_read3 + ((size_t)rb * (2 * HID / 64) + kb + HID / 64) * TILE_B + lin)
            = make_uint4(lo[0], lo[1], lo[2], lo[3]);
    }
}

// --------------- broadcast: out[b,s,:] = tanh(orow + b_dec) ----------------
__global__ void k_broadcast(const float* __restrict__ orow,
                            const float* __restrict__ bdec,
                            float* __restrict__ out)
{
    int t = blockIdx.x * blockDim.x + threadIdx.x;
    if (t < BATCH * DIM / 4) {
        int b = t / (DIM / 4), dq = t % (DIM / 4);
        float4 v = ((const float4*)orow)[(size_t)b * (DIM / 4) + dq];
        float4 bb = ((const float4*)bdec)[dq];
        v.x = tanhf(v.x + bb.x); v.y = tanhf(v.y + bb.y);
        v.z = tanhf(v.z + bb.z); v.w = tanhf(v.w + bb.w);
        float4* o = (float4*)out;
#pragma unroll
        for (int s = 0; s < SEQ; s++)
            o[((size_t)b * SEQ + s) * (DIM / 4) + dq] = v;
    }
}

// ---------------------------------------------------------------------------
extern "C" void kernel_launch(void* const* d_in, const int* in_sizes, int n_in,
                              void* d_out, int out_size)
{
    int i = 1;
    if (in_sizes[1] < 16) i = 2;   // skip scalar 'topk' input if present

    const float* x      = (const float*)d_in[0];
    const float* W_enc  = (const float*)d_in[i++];
    const float* b_enc  = (const float*)d_in[i++];
    const float* w_curv = (const float*)d_in[i++];
    const float* b_curv = (const float*)d_in[i++];
    const float* mem    = (const float*)d_in[i++];
    const float* assoc  = (const float*)d_in[i++];
    const float* W_dec  = (const float*)d_in[i++];
    const float* b_dec  = (const float*)d_in[i++];
    const float* temp   = (const float*)d_in[i++];
    float* out = (float*)d_out;

    bf16 *x3, *We3, *mem3, *as1, *Wd3, *q3, *act1, *read3;
    float *query, *sim, *actB, *orow;
    cudaGetSymbolAddress((void**)&x3,    g_x3);
    cudaGetSymbolAddress((void**)&We3,   g_We3);
    cudaGetSymbolAddress((void**)&mem3,  g_mem3);
    cudaGetSymbolAddress((void**)&as1,   g_as);
    cudaGetSymbolAddress((void**)&Wd3,   g_Wd3);
    cudaGetSymbolAddress((void**)&q3,    g_q3);
    cudaGetSymbolAddress((void**)&act1,  g_act);
    cudaGetSymbolAddress((void**)&read3, g_read3);
    cudaGetSymbolAddress((void**)&query, g_query);
    cudaGetSymbolAddress((void**)&sim,   g_sim);
    cudaGetSymbolAddress((void**)&actB,  g_actB);
    cudaGetSymbolAddress((void**)&orow,  g_orow);

    cudaFuncSetAttribute(k_gemm<0, 3>, cudaFuncAttributeMaxDynamicSharedMemorySize, SMEM_BYTES);
    cudaFuncSetAttribute(k_gemm<1, 3>, cudaFuncAttributeMaxDynamicSharedMemorySize, SMEM_BYTES);
    cudaFuncSetAttribute(k_gemm<0, 1>, cudaFuncAttributeMaxDynamicSharedMemorySize, SMEM_BYTES);

    // side stream + fork/join events (created once, on the un-captured
    // correctness call; only record/wait ops execute during graph capture)
    static cudaStream_t s1 = nullptr;
    static cudaEvent_t evFork = nullptr, evJoin = nullptr;
    if (s1 == nullptr) {
        cudaStreamCreateWithFlags(&s1, cudaStreamNonBlocking);
        cudaEventCreateWithFlags(&evFork, cudaEventDisableTiming);
        cudaEventCreateWithFlags(&evJoin, cudaEventDisableTiming);
    }

    // ---- fork: weight preps on s1, x decomposition (DRAM hog) on main ----
    cudaEventRecord(evFork, 0);
    cudaStreamWaitEvent(s1, evFork, 0);
    k_tdec_t<true><<<dim3(HID / 32, DIM / 32), 256, 0, s1>>>(W_enc, We3, DIM, HID);
    k_dec_t<<<(int)(((long)MS * HID / 8 + 255) / 256), 256, 0, s1>>>(
        mem, mem3, HID, (long)MS * HID / 8);
    k_tdec_t<false><<<dim3(MS / 32, MS / 32), 256, 0, s1>>>(assoc, as1, MS, MS);
    k_tdec_t<true><<<dim3(DIM / 32, HID / 32), 256, 0, s1>>>(W_dec, Wd3, HID, DIM);
    cudaEventRecord(evJoin, s1);

    k_dec_t<<<(int)(((long)BATCH * SEQ * DIM / 8 + 255) / 256), 256>>>(
        x, x3, DIM, (long)BATCH * SEQ * DIM / 8);
    cudaStreamWaitEvent(0, evJoin, 0);   // join before encoder

    // ---- encoder GEMM (bf16x3 fat) + fused tanh/bias/mean ----
    k_gemm<1, 3><<<dim3(HID / 128, BATCH * SEQ / 256), 512, SMEM_BYTES>>>(
        x3, We3, 2 * DIM / 64, 2 * DIM / 64, DIM, nullptr, 0, b_enc, query, q3);
    // ---- sim = query @ mem^T ----
    k_gemm<0, 3><<<dim3(MS / 128, BATCH / 256), 512, SMEM_BYTES>>>(
        q3, mem3, 2 * HID / 64, 2 * HID / 64, HID, sim, MS, nullptr, nullptr, nullptr);
    // ---- fused gate + top-k + softmax #1 ----
    k_simfuse<<<BATCH, 256>>>(sim, query, w_curv, b_curv, temp, act1);
    // ---- assoc GEMM #1 (BK=128) ----
    k_gemm<0, 1><<<dim3(MS / 128, BATCH / 256), 512, SMEM_BYTES>>>(
        act1, as1, MS / 64, MS / 64, MS, actB, MS, nullptr, nullptr, nullptr);
    // ---- softmax #2 -> assoc GEMM #2 ----
    k_softmax_dec<<<BATCH, 256>>>(actB, act1);
    k_gemm<0, 1><<<dim3(MS / 128, BATCH / 256), 512, SMEM_BYTES>>>(
        act1, as1, MS / 64, MS / 64, MS, actB, MS, nullptr, nullptr, nullptr);
    // ---- combine + gather-read ----
    k_combine<<<BATCH, 256>>>(actB, mem);
    // ---- decoder GEMM -> orow ----
    k_gemm<0, 3><<<dim3(DIM / 128, BATCH / 256), 512, SMEM_BYTES>>>(
        read3, Wd3, 2 * HID / 64, 2 * HID / 64, HID, orow, DIM, nullptr, nullptr, nullptr);
    // ---- bias + tanh + broadcast over S ----
    k_broadcast<<<(BATCH * DIM / 4 + 255) / 256, 256>>>(orow, b_dec, out);
}

// round 14
// speedup vs baseline: 1.0017x; 1.0017x over previous
#include <cuda_runtime.h>
#include <cuda_bf16.h>
#include <math.h>
#include <float.h>
#include <stdint.h>

#define BATCH 2048
#define SEQ   32
#define DIM   1024
#define HID   1024
#define MS    4096
#define NK    32

typedef __nv_bfloat16 bf16;

// Tiled layout: tile = 128 rows x 64 cols bf16 = 16KB, SW128-swizzled.
#define TILE_E 8192
#define TILE_B 16384

// ------------------------------- scratch -----------------------------------
__device__ bf16 g_x3[(size_t)BATCH * SEQ * 2 * DIM];
__device__ bf16 g_We3[(size_t)HID * 2 * DIM];
__device__ bf16 g_mem3[(size_t)MS * 2 * HID];
__device__ bf16 g_as[(size_t)MS * MS];
__device__ bf16 g_Wd3[(size_t)DIM * 2 * HID];
__device__ bf16 g_q3[(size_t)BATCH * 2 * HID];
__device__ bf16 g_act[(size_t)BATCH * MS];
__device__ bf16 g_read3[(size_t)BATCH * 2 * HID];
__device__ float g_query[(size_t)BATCH * HID];
__device__ float g_sim[(size_t)BATCH * MS];
__device__ float g_actB[(size_t)BATCH * MS];
__device__ float g_orow[(size_t)BATCH * DIM];
__device__ float g_vals[BATCH * NK];
__device__ int   g_idx[BATCH * NK];

// ------------------------------ helpers ------------------------------------
__device__ __forceinline__ uint32_t s2u(const void* p) {
    uint32_t a;
    asm("{ .reg .u64 t; cvta.to.shared.u64 t, %1; cvt.u32.u64 %0, t; }" : "=r"(a) : "l"(p));
    return a;
}
__device__ __forceinline__ uint32_t swz(uint32_t lin) {
    return lin ^ ((lin >> 3) & 0x70u);
}
__device__ __forceinline__ void ldsm4(uint32_t* r, uint32_t a) {
    asm volatile("ldmatrix.sync.aligned.m8n8.x4.shared.b16 {%0,%1,%2,%3}, [%4];"
        : "=r"(r[0]), "=r"(r[1]), "=r"(r[2]), "=r"(r[3]) : "r"(a));
}
__device__ __forceinline__ void ldsm2(uint32_t* r, uint32_t a) {
    asm volatile("ldmatrix.sync.aligned.m8n8.x2.shared.b16 {%0,%1}, [%2];"
        : "=r"(r[0]), "=r"(r[1]) : "r"(a));
}
__device__ __forceinline__ void mma16816(float* c, const uint32_t* a, const uint32_t* b) {
    asm volatile("mma.sync.aligned.m16n8k16.row.col.f32.bf16.bf16.f32 "
        "{%0,%1,%2,%3}, {%4,%5,%6,%7}, {%8,%9}, {%0,%1,%2,%3};"
        : "+f"(c[0]), "+f"(c[1]), "+f"(c[2]), "+f"(c[3])
        : "r"(a[0]), "r"(a[1]), "r"(a[2]), "r"(a[3]), "r"(b[0]), "r"(b[1]));
}
__device__ __forceinline__ float fast_tanh(float x) {
    float ax = fabsf(x);
    float t = __expf(-2.0f * ax);
    float r = (1.0f - t) / (1.0f + t);
    return copysignf(r, x);
}
__device__ __forceinline__ uint32_t pk2(float a, float b) {
    __nv_bfloat162 h;
    h.x = __float2bfloat16(a); h.y = __float2bfloat16(b);
    return *(uint32_t*)&h;
}

#define MBARRIER_INIT(mb, c) \
    asm volatile("mbarrier.init.shared.b64 [%0], %1;" :: "r"((uint32_t)(mb)), "r"((uint32_t)(c)) : "memory")
#define MBAR_ARRIVE_EXPECT(mb, tx) \
    asm volatile("mbarrier.arrive.expect_tx.shared.b64 _, [%0], %1;" :: "r"((uint32_t)(mb)), "r"((uint32_t)(tx)) : "memory")
#define BULK_G2S(dst, src, bytes, mb) \
    asm volatile("cp.async.bulk.shared::cluster.global.mbarrier::complete_tx::bytes [%0], [%1], %2, [%3];" \
        :: "r"((uint32_t)(dst)), "l"(src), "r"((uint32_t)(bytes)), "r"((uint32_t)(mb)) : "memory")
#define MBARRIER_WAIT_PARITY(mb, ph) do {                                              \
    uint32_t _mb = (uint32_t)(mb); uint32_t _ph = (uint32_t)(ph); uint32_t _done;      \
    asm volatile("{\n .reg .pred p;\n"                                                 \
        " mbarrier.try_wait.parity.acquire.cta.shared::cta.b64 p, [%1], %2;\n"         \
        " selp.b32 %0, 1, 0, p;\n}"                                                    \
        : "=r"(_done) : "r"(_mb), "r"(_ph) : "memory");                                \
    if (!_done) {                                                                      \
        asm volatile("{\n .reg .pred P1;\n"                                            \
            "WL_%=:\n"                                                                 \
            " mbarrier.try_wait.parity.acquire.cta.shared::cta.b64 P1, [%0], %1, 0x989680;\n" \
            " @P1 bra.uni WD_%=;\n bra.uni WL_%=;\nWD_%=:\n}"                          \
            :: "r"(_mb), "r"(_ph) : "memory");                                         \
    }                                                                                  \
} while (0)

// ----------------------------- GEMM ----------------------------------------
// C[M,N] = A @ B^T, tiled-swizzled bf16 operands.
// BM=256, BN=128, BK=64. 512 threads, 16 warps 4x4, warp tile 64x32.
// TERMS==3: fat chunks {A hi,lo}x2 + {B hi,lo} (96KB), 3 passes, 2 stages.
// TERMS==1: plain bf16, 48KB chunks, 4 stages.
// EPI: 0 = fp32 C store; 1 = encoder tanh+bias+mean -> query/q3.
#define SMEM_BYTES (1024 + 196608)

template <int EPI, int TERMS>
__global__ void __launch_bounds__(512, 1)
k_gemm(const bf16* __restrict__ A, const bf16* __restrict__ B,
       int nkbA, int nkbB, int K,
       float* __restrict__ C, int Nst,
       const float* __restrict__ bias,
       float* __restrict__ qout, bf16* __restrict__ q3out)
{
    extern __shared__ char smem[];
    const uint32_t sb = s2u(smem);
    const int tid = threadIdx.x, wid = tid >> 5, lane = tid & 31;
    const int wr = wid >> 2, wc = wid & 3;
    const int m0 = blockIdx.y * 256, n0 = blockIdx.x * 128;
    const int Kb = K / 64;
    const int rbA0 = blockIdx.y * 2;
    const int nb = blockIdx.x;

    if (tid == 0) {
#pragma unroll
        for (int s = 0; s < 4; s++) MBARRIER_INIT(sb + s * 8, 1);
    }
    __syncthreads();

    const uint32_t aTileSel = (wr >= 2) ? (uint32_t)TILE_B : 0u;
    uint32_t alin[4], blin[4];
#pragma unroll
    for (int mi = 0; mi < 4; mi++)
        alin[mi] = (uint32_t)(((wr & 1) * 64) + mi * 16 + (lane & 15)) * 128u + (uint32_t)(lane >> 4) * 16u;
#pragma unroll
    for (int ni = 0; ni < 4; ni++)
        blin[ni] = (uint32_t)(wc * 32 + ni * 8 + (lane & 7)) * 128u + (uint32_t)((lane >> 3) & 1) * 16u;

    float acc[4][4][4];
#pragma unroll
    for (int a = 0; a < 4; a++)
#pragma unroll
        for (int b = 0; b < 4; b++)
#pragma unroll
            for (int c = 0; c < 4; c++) acc[a][b][c] = 0.f;

    if (TERMS == 3) {
        const int NC = Kb;
        if (tid == 0) {
#pragma unroll
            for (int c0 = 0; c0 < 2; c0++) {
                if (c0 >= NC) break;
                uint32_t mb = sb + (uint32_t)c0 * 8;
                uint32_t dst = sb + 1024u + (uint32_t)c0 * 98304u;
                MBAR_ARRIVE_EXPECT(mb, 98304u);
                BULK_G2S(dst,           A + ((size_t)rbA0 * nkbA + c0) * TILE_E, TILE_B, mb);
                BULK_G2S(dst + 16384u,  A + ((size_t)(rbA0 + 1) * nkbA + c0) * TILE_E, TILE_B, mb);
                BULK_G2S(dst + 32768u,  A + ((size_t)rbA0 * nkbA + c0 + Kb) * TILE_E, TILE_B, mb);
                BULK_G2S(dst + 49152u,  A + ((size_t)(rbA0 + 1) * nkbA + c0 + Kb) * TILE_E, TILE_B, mb);
                BULK_G2S(dst + 65536u,  B + ((size_t)nb * nkbB + c0) * TILE_E, TILE_B, mb);
                BULK_G2S(dst + 81920u,  B + ((size_t)nb * nkbB + c0 + Kb) * TILE_E, TILE_B, mb);
            }
        }
        for (int c = 0; c < NC; c++) {
            int s = c & 1;
            MBARRIER_WAIT_PARITY(sb + s * 8, (c >> 1) & 1);
            const uint32_t stg = sb + 1024u + (uint32_t)s * 98304u;
            const uint32_t Ah = stg + aTileSel;
            const uint32_t Al = stg + 32768u + aTileSel;
            const uint32_t Bh = stg + 65536u;
            const uint32_t Bl = stg + 81920u;
#pragma unroll
            for (int ks = 0; ks < 4; ks++) {
                uint32_t af[4][4], bh[4][2], bl[4][2];
#pragma unroll
                for (int mi = 0; mi < 4; mi++) ldsm4(af[mi], Ah + swz(alin[mi] + ks * 32u));
#pragma unroll
                for (int ni = 0; ni < 4; ni++) ldsm2(bh[ni], Bh + swz(blin[ni] + ks * 32u));
#pragma unroll
                for (int ni = 0; ni < 4; ni++) ldsm2(bl[ni], Bl + swz(blin[ni] + ks * 32u));
#pragma unroll
                for (int mi = 0; mi < 4; mi++)
#pragma unroll
                    for (int ni = 0; ni < 4; ni++) mma16816(acc[mi][ni], af[mi], bh[ni]);
#pragma unroll
                for (int mi = 0; mi < 4; mi++)
#pragma unroll
                    for (int ni = 0; ni < 4; ni++) mma16816(acc[mi][ni], af[mi], bl[ni]);
#pragma unroll
                for (int mi = 0; mi < 4; mi++) ldsm4(af[mi], Al + swz(alin[mi] + ks * 32u));
#pragma unroll
                for (int mi = 0; mi < 4; mi++)
#pragma unroll
                    for (int ni = 0; ni < 4; ni++) mma16816(acc[mi][ni], af[mi], bh[ni]);
            }
            __syncthreads();
            if (c + 2 < NC && tid == 0) {
                int cn = c + 2;
                uint32_t mb = sb + (uint32_t)s * 8;
                uint32_t dst = sb + 1024u + (uint32_t)s * 98304u;
                MBAR_ARRIVE_EXPECT(mb, 98304u);
                BULK_G2S(dst,           A + ((size_t)rbA0 * nkbA + cn) * TILE_E, TILE_B, mb);
                BULK_G2S(dst + 16384u,  A + ((size_t)(rbA0 + 1) * nkbA + cn) * TILE_E, TILE_B, mb);
                BULK_G2S(dst + 32768u,  A + ((size_t)rbA0 * nkbA + cn + Kb) * TILE_E, TILE_B, mb);
                BULK_G2S(dst + 49152u,  A + ((size_t)(rbA0 + 1) * nkbA + cn + Kb) * TILE_E, TILE_B, mb);
                BULK_G2S(dst + 65536u,  B + ((size_t)nb * nkbB + cn) * TILE_E, TILE_B, mb);
                BULK_G2S(dst + 81920u,  B + ((size_t)nb * nkbB + cn + Kb) * TILE_E, TILE_B, mb);
            }
        }
    } else {
        const int NC = Kb;
        if (tid == 0) {
#pragma unroll
            for (int c0 = 0; c0 < 3; c0++) {
                if (c0 >= NC) break;
                uint32_t mb = sb + (uint32_t)c0 * 8;
                uint32_t dst = sb + 1024u + (uint32_t)c0 * 49152u;
                MBAR_ARRIVE_EXPECT(mb, 49152u);
                BULK_G2S(dst,              A + ((size_t)rbA0 * nkbA + c0) * TILE_E, TILE_B, mb);
                BULK_G2S(dst + TILE_B,     A + ((size_t)(rbA0 + 1) * nkbA + c0) * TILE_E, TILE_B, mb);
                BULK_G2S(dst + 2 * TILE_B, B + ((size_t)nb * nkbB + c0) * TILE_E, TILE_B, mb);
            }
        }
        for (int c = 0; c < NC; c++) {
            int s = c & 3;
            MBARRIER_WAIT_PARITY(sb + s * 8, (c >> 2) & 1);
            const uint32_t As = sb + 1024u + (uint32_t)s * 49152u + aTileSel;
            const uint32_t Bs = sb + 1024u + (uint32_t)s * 49152u + 2u * TILE_B;
#pragma unroll
            for (int ks = 0; ks < 4; ks++) {
                uint32_t af[4][4], bfr[4][2];
#pragma unroll
                for (int mi = 0; mi < 4; mi++) ldsm4(af[mi], As + swz(alin[mi] + ks * 32u));
#pragma unroll
                for (int ni = 0; ni < 4; ni++) ldsm2(bfr[ni], Bs + swz(blin[ni] + ks * 32u));
#pragma unroll
                for (int mi = 0; mi < 4; mi++)
#pragma unroll
                    for (int ni = 0; ni < 4; ni++) mma16816(acc[mi][ni], af[mi], bfr[ni]);
            }
            __syncthreads();
            if (c + 3 < NC && tid == 0) {
                int cn = c + 3;
                int sn = cn & 3;
                uint32_t mb = sb + (uint32_t)sn * 8;
                uint32_t dst = sb + 1024u + (uint32_t)sn * 49152u;
                MBAR_ARRIVE_EXPECT(mb, 49152u);
                BULK_G2S(dst,              A + ((size_t)rbA0 * nkbA + cn) * TILE_E, TILE_B, mb);
                BULK_G2S(dst + TILE_B,     A + ((size_t)(rbA0 + 1) * nkbA + cn) * TILE_E, TILE_B, mb);
                BULK_G2S(dst + 2 * TILE_B, B + ((size_t)nb * nkbB + cn) * TILE_E, TILE_B, mb);
            }
        }
    }

    if (EPI == 0) {
#pragma unroll
        for (int mi = 0; mi < 4; mi++) {
            int r = m0 + wr * 64 + mi * 16 + (lane >> 2);
#pragma unroll
            for (int ni = 0; ni < 4; ni++) {
                int col = n0 + wc * 32 + ni * 8 + 2 * (lane & 3);
                *(float2*)&C[(size_t)r * Nst + col] = make_float2(acc[mi][ni][0], acc[mi][ni][1]);
                *(float2*)&C[(size_t)(r + 8) * Nst + col] = make_float2(acc[mi][ni][2], acc[mi][ni][3]);
            }
        }
    } else {
        // rows = batch*SEQ; 32-row group = one batch; warp holds 2 batches.
#pragma unroll
        for (int b = 0; b < 2; b++) {
            int batch = m0 / 32 + wr * 2 + b;
#pragma unroll
            for (int ni = 0; ni < 4; ni++) {
                int col0 = n0 + wc * 32 + ni * 8 + 2 * (lane & 3);
                float bi0 = bias[col0], bi1 = bias[col0 + 1];
                float s0 = 0.f, s1 = 0.f;
#pragma unroll
                for (int mh = 0; mh < 2; mh++) {
                    float* cc = acc[b * 2 + mh][ni];
                    s0 += fast_tanh(cc[0] + bi0) + fast_tanh(cc[2] + bi0);
                    s1 += fast_tanh(cc[1] + bi1) + fast_tanh(cc[3] + bi1);
                }
#pragma unroll
                for (int o = 4; o <= 16; o <<= 1) {
                    s0 += __shfl_xor_sync(0xffffffffu, s0, o);
                    s1 += __shfl_xor_sync(0xffffffffu, s1, o);
                }
                if (lane < 4) {
                    float q0 = s0 * (1.0f / SEQ), q1 = s1 * (1.0f / SEQ);
                    qout[(size_t)batch * HID + col0] = q0;
                    qout[(size_t)batch * HID + col0 + 1] = q1;
                    uint32_t lin = swz(((uint32_t)(batch & 127) << 7) + ((uint32_t)(col0 & 63) << 1));
                    int rb = batch >> 7, kb = col0 >> 6;
                    char* th = (char*)q3out + ((size_t)rb * (2 * HID / 64) + kb) * TILE_B + lin;
                    char* tl = (char*)q3out + ((size_t)rb * (2 * HID / 64) + kb + HID / 64) * TILE_B + lin;
                    bf16 h0 = __float2bfloat16(q0), h1 = __float2bfloat16(q1);
                    *(uint32_t*)th = pk2(q0, q1);
                    *(uint32_t*)tl = pk2(q0 - __bfloat162float(h0), q1 - __bfloat162float(h1));
                }
            }
        }
    }
}

// ---------------------- prep: row-major fp32 -> tiled hi|lo ----------------
__global__ void k_dec_t(const float* __restrict__ in, bf16* __restrict__ out,
                        int K, long nGran)
{
    long g = (long)blockIdx.x * 256 + threadIdx.x;
    if (g >= nGran) return;
    int perRow = K / 8;
    long r = g / perRow;
    int c = (int)(g % perRow) * 8;
    float4 v0 = *(const float4*)(in + r * K + c);
    float4 v1 = *(const float4*)(in + r * K + c + 4);
    float f[8] = {v0.x, v0.y, v0.z, v0.w, v1.x, v1.y, v1.z, v1.w};
    uint32_t hi[4], lo[4];
#pragma unroll
    for (int j = 0; j < 4; j++) {
        bf16 h0 = __float2bfloat16(f[2 * j]), h1 = __float2bfloat16(f[2 * j + 1]);
        __nv_bfloat162 hp; hp.x = h0; hp.y = h1;
        hi[j] = *(uint32_t*)&hp;
        lo[j] = pk2(f[2 * j] - __bfloat162float(h0), f[2 * j + 1] - __bfloat162float(h1));
    }
    int rb = (int)(r >> 7), kb = c >> 6, kbT = 2 * K / 64;
    uint32_t lin = swz(((uint32_t)(r & 127) << 7) + ((uint32_t)(c & 63) << 1));
    *(uint4*)((char*)out + ((size_t)rb * kbT + kb) * TILE_B + lin) = make_uint4(hi[0], hi[1], hi[2], hi[3]);
    *(uint4*)((char*)out + ((size_t)rb * kbT + kb + K / 64) * TILE_B + lin) = make_uint4(lo[0], lo[1], lo[2], lo[3]);
}

// ------------- prep: transpose fp32 [K][N] -> tiled rows=n ------------------
template <bool LO>
__global__ void k_tdec_t(const float* __restrict__ in, bf16* __restrict__ out,
                         int K, int N)
{
    __shared__ float tile[32][33];
    int n0 = blockIdx.x * 32, k0 = blockIdx.y * 32;
    int tx = threadIdx.x & 31, ty = threadIdx.x >> 5;
    for (int r = ty; r < 32; r += 8)
        tile[r][tx] = in[(size_t)(k0 + r) * N + n0 + tx];
    __syncthreads();
    int t = threadIdx.x;
    if (t < 128) {
        int nl = t & 31, kg = t >> 5;
        float f[8];
#pragma unroll
        for (int j = 0; j < 8; j++) f[j] = tile[kg * 8 + j][nl];
        int n = n0 + nl, k = k0 + kg * 8;
        uint32_t hi[4], lo[4];
#pragma unroll
        for (int j = 0; j < 4; j++) {
            bf16 h0 = __float2bfloat16(f[2 * j]), h1 = __float2bfloat16(f[2 * j + 1]);
            __nv_bfloat162 hp; hp.x = h0; hp.y = h1;
            hi[j] = *(uint32_t*)&hp;
            if (LO)
                lo[j] = pk2(f[2 * j] - __bfloat162float(h0), f[2 * j + 1] - __bfloat162float(h1));
        }
        int rb = n >> 7, kb = k >> 6;
        int kbT = LO ? 2 * K / 64 : K / 64;
        uint32_t lin = swz(((uint32_t)(n & 127) << 7) + ((uint32_t)(k & 63) << 1));
        *(uint4*)((char*)out + ((size_t)rb * kbT + kb) * TILE_B + lin) = make_uint4(hi[0], hi[1], hi[2], hi[3]);
        if (LO)
            *(uint4*)((char*)out + ((size_t)rb * kbT + kb + K / 64) * TILE_B + lin) = make_uint4(lo[0], lo[1], lo[2], lo[3]);
    }
}

// ---- fused: gate + top-k + softmax over one sim row (block = one batch) ----
__global__ void k_simfuse(const float* __restrict__ sim,
                          const float* __restrict__ query,
                          const float* __restrict__ w_curv,
                          const float* __restrict__ b_curv,
                          const float* __restrict__ temperature,
                          bf16* __restrict__ out)
{
    __shared__ float sv[MS];
    __shared__ float red[256];
    __shared__ float cv[256];
    __shared__ int   ci[256];
    __shared__ float s_scale;

    int b = blockIdx.x, tid = threadIdx.x;
    int w = tid >> 5, lane = tid & 31;

    const float* row = sim + (size_t)b * MS;
    float mx = -FLT_MAX;
    for (int i = tid; i < MS; i += 256) { float v = row[i]; sv[i] = v; mx = fmaxf(mx, v); }

    float gs = 0.f;
    for (int h = tid; h < HID; h += 256)
        gs += query[(size_t)b * HID + h] * w_curv[h];
    red[tid] = gs; __syncthreads();
    for (int off = 128; off; off >>= 1) { if (tid < off) red[tid] += red[tid + off]; __syncthreads(); }
    if (tid == 0) {
        float gate = 1.0f / (1.0f + expf(-(red[0] + b_curv[0])));
        s_scale = (0.5f + gate) / fmaxf(temperature[0], 1e-6f);
    }
    __syncthreads();
    float scale = s_scale;

    red[tid] = mx; __syncthreads();
    for (int off = 128; off; off >>= 1) { if (tid < off) red[tid] = fmaxf(red[tid], red[tid + off]); __syncthreads(); }
    mx = red[0]; __syncthreads();

    float v[16];
#pragma unroll
    for (int j = 0; j < 16; j++) v[j] = sv[w * 512 + j * 32 + lane] * scale;

    for (int it = 0; it < NK; it++) {
        float bv = -FLT_MAX; int bj = 0;
#pragma unroll
        for (int j = 0; j < 16; j++)
            if (v[j] > bv) { bv = v[j]; bj = j; }
        int bi = w * 512 + bj * 32 + lane;
#pragma unroll
        for (int o = 16; o; o >>= 1) {
            float ov = __shfl_xor_sync(0xffffffffu, bv, o);
            int   oi = __shfl_xor_sync(0xffffffffu, bi, o);
            if (ov > bv || (ov == bv && oi < bi)) { bv = ov; bi = oi; }
        }
        if ((bi & 31) == lane) v[(bi >> 5) & 15] = -FLT_MAX;
        if (lane == 0) { cv[w * 32 + it] = bv; ci[w * 32 + it] = bi; }
    }
    __syncthreads();

    if (w == 0) {
        float pv[8]; int pi[8];
#pragma unroll
        for (int j = 0; j < 8; j++) { pv[j] = cv[lane + j * 32]; pi[j] = ci[lane + j * 32]; }
        for (int k = 0; k < NK; k++) {
            float bv = -FLT_MAX; int bi = 0x7FFFFFFF;
#pragma unroll
            for (int j = 0; j < 8; j++)
                if (pv[j] > bv || (pv[j] == bv && pi[j] < bi)) { bv = pv[j]; bi = pi[j]; }
#pragma unroll
            for (int o = 16; o; o >>= 1) {
                float ov = __shfl_xor_sync(0xffffffffu, bv, o);
                int   oi = __shfl_xor_sync(0xffffffffu, bi, o);
                if (ov > bv || (ov == bv && oi < bi)) { bv = ov; bi = oi; }
            }
#pragma unroll
            for (int j = 0; j < 8; j++)
                if (pi[j] == bi) pv[j] = -FLT_MAX;
            if (lane == 0) {
                g_vals[(size_t)b * NK + k] = bv;
                g_idx [(size_t)b * NK + k] = bi;
            }
        }
    }
    __syncthreads();

    float s = 0.f;
    for (int i = tid; i < MS; i += 256) { float e = expf(sv[i] - mx); sv[i] = e; s += e; }
    red[tid] = s; __syncthreads();
    for (int off = 128; off; off >>= 1) { if (tid < off) red[tid] += red[tid + off]; __syncthreads(); }
    float inv = 1.0f / red[0];
    int rb = b >> 7;
    uint32_t rlin = (uint32_t)(b & 127) << 7;
    for (int gI = tid; gI < MS / 8; gI += 256) {
        int c = gI * 8;
        uint32_t hi[4];
#pragma unroll
        for (int j = 0; j < 4; j++)
            hi[j] = pk2(sv[c + 2 * j] * inv, sv[c + 2 * j + 1] * inv);
        uint32_t lin = swz(rlin + ((uint32_t)(c & 63) << 1));
        *(uint4*)((char*)out + ((size_t)rb * (MS / 64) + (c >> 6)) * TILE_B + lin)
            = make_uint4(hi[0], hi[1], hi[2], hi[3]);
    }
}

// ------------- softmax over M=4096 -> tiled bf16 (hi only) ------------------
__global__ void k_softmax_dec(const float* __restrict__ in, bf16* __restrict__ out)
{
    __shared__ float sv[MS];
    __shared__ float red[256];
    int b = blockIdx.x, tid = threadIdx.x;
    const float* row = in + (size_t)b * MS;
    float mx = -FLT_MAX;
    for (int i = tid; i < MS; i += 256) { float v = row[i]; sv[i] = v; mx = fmaxf(mx, v); }
    red[tid] = mx; __syncthreads();
    for (int off = 128; off; off >>= 1) { if (tid < off) red[tid] = fmaxf(red[tid], red[tid + off]); __syncthreads(); }
    mx = red[0]; __syncthreads();
    float s = 0.f;
    for (int i = tid; i < MS; i += 256) { float e = expf(sv[i] - mx); sv[i] = e; s += e; }
    red[tid] = s; __syncthreads();
    for (int off = 128; off; off >>= 1) { if (tid < off) red[tid] += red[tid + off]; __syncthreads(); }
    float inv = 1.0f / red[0];
    int rb = b >> 7;
    uint32_t rlin = (uint32_t)(b & 127) << 7;
    for (int gI = tid; gI < MS / 8; gI += 256) {
        int c = gI * 8;
        uint32_t hi[4];
#pragma unroll
        for (int j = 0; j < 4; j++)
            hi[j] = pk2(sv[c + 2 * j] * inv, sv[c + 2 * j + 1] * inv);
        uint32_t lin = swz(rlin + ((uint32_t)(c & 63) << 1));
        *(uint4*)((char*)out + ((size_t)rb * (MS / 64) + (c >> 6)) * TILE_B + lin)
            = make_uint4(hi[0], hi[1], hi[2], hi[3]);
    }
}

// ------- combine: softmax(vals + act[idx]); read3 (tiled hi|lo) -------------
__global__ void k_combine(const float* __restrict__ act,
                          const float* __restrict__ mem)
{
    __shared__ float comb[NK];
    __shared__ int   sidx[NK];
    int b = blockIdx.x, tid = threadIdx.x;
    if (tid < NK) {
        int id = g_idx[(size_t)b * NK + tid];
        sidx[tid] = id;
        float t = g_vals[(size_t)b * NK + tid] + act[(size_t)b * MS + id];
        float m = t;
#pragma unroll
        for (int o = 16; o; o >>= 1) m = fmaxf(m, __shfl_xor_sync(0xffffffffu, m, o));
        float e = expf(t - m);
        float s = e;
#pragma unroll
        for (int o = 16; o; o >>= 1) s += __shfl_xor_sync(0xffffffffu, s, o);
        comb[tid] = e / s;
    }
    __syncthreads();
    int rb = b >> 7;
    uint32_t rlin = (uint32_t)(b & 127) << 7;
    if (tid < HID / 8) {
        int h0 = tid * 8;
        float a[8] = {0, 0, 0, 0, 0, 0, 0, 0};
#pragma unroll
        for (int k = 0; k < NK; k++) {
            float cb = comb[k];
            const float4* mr = (const float4*)(mem + (size_t)sidx[k] * HID + h0);
            float4 m0 = mr[0], m1 = mr[1];
            a[0] += cb * m0.x; a[1] += cb * m0.y; a[2] += cb * m0.z; a[3] += cb * m0.w;
            a[4] += cb * m1.x; a[5] += cb * m1.y; a[6] += cb * m1.z; a[7] += cb * m1.w;
        }
        uint32_t hi[4], lo[4];
#pragma unroll
        for (int j = 0; j < 4; j++) {
            bf16 h0b = __float2bfloat16(a[2 * j]), h1b = __float2bfloat16(a[2 * j + 1]);
            __nv_bfloat162 hp; hp.x = h0b; hp.y = h1b;
            hi[j] = *(uint32_t*)&hp;
            lo[j] = pk2(a[2 * j] - __bfloat162float(h0b), a[2 * j + 1] - __bfloat162float(h1b));
        }
        int kb = h0 >> 6;
        uint32_t lin = swz(rlin + ((uint32_t)(h0 & 63) << 1));
        *(uint4*)((char*)g_read3 + ((size_t)rb * (2 * HID / 64) + kb) * TILE_B + lin)
            = make_uint4(hi[0], hi[1], hi[2], hi[3]);
        *(uint4*)((char*)g_read3 + ((size_t)rb * (2 * HID / 64) + kb + HID / 64) * TILE_B + lin)
            = make_uint4(lo[0], lo[1], lo[2], lo[3]);
    }
}

// --------------- broadcast: out[b,s,:] = tanh(orow + b_dec) ----------------
__global__ void k_broadcast(const float* __restrict__ orow,
                            const float* __restrict__ bdec,
                            float* __restrict__ out)
{
    int t = blockIdx.x * blockDim.x + threadIdx.x;
    if (t < BATCH * DIM / 4) {
        int b = t / (DIM / 4), dq = t % (DIM / 4);
        float4 v = ((const float4*)orow)[(size_t)b * (DIM / 4) + dq];
        float4 bb = ((const float4*)bdec)[dq];
        v.x = tanhf(v.x + bb.x); v.y = tanhf(v.y + bb.y);
        v.z = tanhf(v.z + bb.z); v.w = tanhf(v.w + bb.w);
        float4* o = (float4*)out;
#pragma unroll
        for (int s = 0; s < SEQ; s++)
            o[((size_t)b * SEQ + s) * (DIM / 4) + dq] = v;
    }
}

// ---------------------------------------------------------------------------
extern "C" void kernel_launch(void* const* d_in, const int* in_sizes, int n_in,
                              void* d_out, int out_size)
{
    int i = 1;
    if (in_sizes[1] < 16) i = 2;   // skip scalar 'topk' input if present

    const float* x      = (const float*)d_in[0];
    const float* W_enc  = (const float*)d_in[i++];
    const float* b_enc  = (const float*)d_in[i++];
    const float* w_curv = (const float*)d_in[i++];
    const float* b_curv = (const float*)d_in[i++];
    const float* mem    = (const float*)d_in[i++];
    const float* assoc  = (const float*)d_in[i++];
    const float* W_dec  = (const float*)d_in[i++];
    const float* b_dec  = (const float*)d_in[i++];
    const float* temp   = (const float*)d_in[i++];
    float* out = (float*)d_out;

    bf16 *x3, *We3, *mem3, *as1, *Wd3, *q3, *act1, *read3;
    float *query, *sim, *actB, *orow;
    cudaGetSymbolAddress((void**)&x3,    g_x3);
    cudaGetSymbolAddress((void**)&We3,   g_We3);
    cudaGetSymbolAddress((void**)&mem3,  g_mem3);
    cudaGetSymbolAddress((void**)&as1,   g_as);
    cudaGetSymbolAddress((void**)&Wd3,   g_Wd3);
    cudaGetSymbolAddress((void**)&q3,    g_q3);
    cudaGetSymbolAddress((void**)&act1,  g_act);
    cudaGetSymbolAddress((void**)&read3, g_read3);
    cudaGetSymbolAddress((void**)&query, g_query);
    cudaGetSymbolAddress((void**)&sim,   g_sim);
    cudaGetSymbolAddress((void**)&actB,  g_actB);
    cudaGetSymbolAddress((void**)&orow,  g_orow);

    cudaFuncSetAttribute(k_gemm<0, 3>, cudaFuncAttributeMaxDynamicSharedMemorySize, SMEM_BYTES);
    cudaFuncSetAttribute(k_gemm<1, 3>, cudaFuncAttributeMaxDynamicSharedMemorySize, SMEM_BYTES);
    cudaFuncSetAttribute(k_gemm<0, 1>, cudaFuncAttributeMaxDynamicSharedMemorySize, SMEM_BYTES);

    // side stream + fork/join events (created once, on the un-captured
    // correctness call; only record/wait ops execute during graph capture)
    static cudaStream_t s1 = nullptr;
    static cudaEvent_t evFork = nullptr, evJoin = nullptr;
    if (s1 == nullptr) {
        cudaStreamCreateWithFlags(&s1, cudaStreamNonBlocking);
        cudaEventCreateWithFlags(&evFork, cudaEventDisableTiming);
        cudaEventCreateWithFlags(&evJoin, cudaEventDisableTiming);
    }

    // ---- fork: weight preps on s1, x decomposition (DRAM hog) on main ----
    cudaEventRecord(evFork, 0);
    cudaStreamWaitEvent(s1, evFork, 0);
    k_tdec_t<true><<<dim3(HID / 32, DIM / 32), 256, 0, s1>>>(W_enc, We3, DIM, HID);
    k_dec_t<<<(int)(((long)MS * HID / 8 + 255) / 256), 256, 0, s1>>>(
        mem, mem3, HID, (long)MS * HID / 8);
    k_tdec_t<false><<<dim3(MS / 32, MS / 32), 256, 0, s1>>>(assoc, as1, MS, MS);
    k_tdec_t<true><<<dim3(DIM / 32, HID / 32), 256, 0, s1>>>(W_dec, Wd3, HID, DIM);
    cudaEventRecord(evJoin, s1);

    k_dec_t<<<(int)(((long)BATCH * SEQ * DIM / 8 + 255) / 256), 256>>>(
        x, x3, DIM, (long)BATCH * SEQ * DIM / 8);
    cudaStreamWaitEvent(0, evJoin, 0);   // join before encoder

    // ---- encoder GEMM (bf16x3 fat) + fused tanh/bias/mean ----
    k_gemm<1, 3><<<dim3(HID / 128, BATCH * SEQ / 256), 512, SMEM_BYTES>>>(
        x3, We3, 2 * DIM / 64, 2 * DIM / 64, DIM, nullptr, 0, b_enc, query, q3);
    // ---- sim = query @ mem^T ----
    k_gemm<0, 3><<<dim3(MS / 128, BATCH / 256), 512, SMEM_BYTES>>>(
        q3, mem3, 2 * HID / 64, 2 * HID / 64, HID, sim, MS, nullptr, nullptr, nullptr);
    // ---- fused gate + top-k + softmax #1 ----
    k_simfuse<<<BATCH, 256>>>(sim, query, w_curv, b_curv, temp, act1);
    // ---- assoc GEMM #1 ----
    k_gemm<0, 1><<<dim3(MS / 128, BATCH / 256), 512, SMEM_BYTES>>>(
        act1, as1, MS / 64, MS / 64, MS, actB, MS, nullptr, nullptr, nullptr);
    // ---- softmax #2 -> assoc GEMM #2 ----
    k_softmax_dec<<<BATCH, 256>>>(actB, act1);
    k_gemm<0, 1><<<dim3(MS / 128, BATCH / 256), 512, SMEM_BYTES>>>(
        act1, as1, MS / 64, MS / 64, MS, actB, MS, nullptr, nullptr, nullptr);
    // ---- combine + gather-read ----
    k_combine<<<BATCH, 256>>>(actB, mem);
    // ---- decoder GEMM -> orow ----
    k_gemm<0, 3><<<dim3(DIM / 128, BATCH / 256), 512, SMEM_BYTES>>>(
        read3, Wd3, 2 * HID / 64, 2 * HID / 64, HID, orow, DIM, nullptr, nullptr, nullptr);
    // ---- bias + tanh + broadcast over S ----
    k_broadcast<<<(BATCH * DIM / 4 + 255) / 256, 256>>>(orow, b_dec, out);
}

// round 15
// speedup vs baseline: 1.0195x; 1.0177x over previous
#include <cuda_runtime.h>
#include <cuda_bf16.h>
#include <math.h>
#include <float.h>
#include <stdint.h>

#define BATCH 2048
#define SEQ   32
#define DIM   1024
#define HID   1024
#define MS    4096
#define NK    32

typedef __nv_bfloat16 bf16;

// Tiled layout: tile = 128 rows x 64 cols bf16 = 16KB, SW128-swizzled.
#define TILE_E 8192
#define TILE_B 16384

// ------------------------------- scratch -----------------------------------
__device__ bf16 g_x3[(size_t)BATCH * SEQ * 2 * DIM];
__device__ bf16 g_We3[(size_t)HID * 2 * DIM];
__device__ bf16 g_mem3[(size_t)MS * 2 * HID];
__device__ bf16 g_as[(size_t)MS * MS];
__device__ bf16 g_Wd3[(size_t)DIM * 2 * HID];
__device__ bf16 g_q3[(size_t)BATCH * 2 * HID];
__device__ bf16 g_act[(size_t)BATCH * MS];
__device__ bf16 g_read3[(size_t)BATCH * 2 * HID];
__device__ float g_query[(size_t)BATCH * HID];
__device__ float g_sim[(size_t)BATCH * MS];
__device__ float g_actB[(size_t)BATCH * MS];
__device__ float g_orow[(size_t)BATCH * DIM];
__device__ float g_vals[BATCH * NK];
__device__ int   g_idx[BATCH * NK];

// ------------------------------ helpers ------------------------------------
__device__ __forceinline__ uint32_t s2u(const void* p) {
    uint32_t a;
    asm("{ .reg .u64 t; cvta.to.shared.u64 t, %1; cvt.u32.u64 %0, t; }" : "=r"(a) : "l"(p));
    return a;
}
__device__ __forceinline__ uint32_t swz(uint32_t lin) {
    return lin ^ ((lin >> 3) & 0x70u);
}
__device__ __forceinline__ void ldsm4(uint32_t* r, uint32_t a) {
    asm volatile("ldmatrix.sync.aligned.m8n8.x4.shared.b16 {%0,%1,%2,%3}, [%4];"
        : "=r"(r[0]), "=r"(r[1]), "=r"(r[2]), "=r"(r[3]) : "r"(a));
}
__device__ __forceinline__ void ldsm2(uint32_t* r, uint32_t a) {
    asm volatile("ldmatrix.sync.aligned.m8n8.x2.shared.b16 {%0,%1}, [%2];"
        : "=r"(r[0]), "=r"(r[1]) : "r"(a));
}
__device__ __forceinline__ void mma16816(float* c, const uint32_t* a, const uint32_t* b) {
    asm volatile("mma.sync.aligned.m16n8k16.row.col.f32.bf16.bf16.f32 "
        "{%0,%1,%2,%3}, {%4,%5,%6,%7}, {%8,%9}, {%0,%1,%2,%3};"
        : "+f"(c[0]), "+f"(c[1]), "+f"(c[2]), "+f"(c[3])
        : "r"(a[0]), "r"(a[1]), "r"(a[2]), "r"(a[3]), "r"(b[0]), "r"(b[1]));
}
__device__ __forceinline__ float fast_tanh(float x) {
    float ax = fabsf(x);
    float t = __expf(-2.0f * ax);
    float r = (1.0f - t) / (1.0f + t);
    return copysignf(r, x);
}
__device__ __forceinline__ uint32_t pk2(float a, float b) {
    __nv_bfloat162 h;
    h.x = __float2bfloat16(a); h.y = __float2bfloat16(b);
    return *(uint32_t*)&h;
}

#define MBARRIER_INIT(mb, c) \
    asm volatile("mbarrier.init.shared.b64 [%0], %1;" :: "r"((uint32_t)(mb)), "r"((uint32_t)(c)) : "memory")
#define MBAR_ARRIVE_EXPECT(mb, tx) \
    asm volatile("mbarrier.arrive.expect_tx.shared.b64 _, [%0], %1;" :: "r"((uint32_t)(mb)), "r"((uint32_t)(tx)) : "memory")
#define BULK_G2S(dst, src, bytes, mb) \
    asm volatile("cp.async.bulk.shared::cluster.global.mbarrier::complete_tx::bytes [%0], [%1], %2, [%3];" \
        :: "r"((uint32_t)(dst)), "l"(src), "r"((uint32_t)(bytes)), "r"((uint32_t)(mb)) : "memory")
#define MBARRIER_WAIT_PARITY(mb, ph) do {                                              \
    uint32_t _mb = (uint32_t)(mb); uint32_t _ph = (uint32_t)(ph); uint32_t _done;      \
    asm volatile("{\n .reg .pred p;\n"                                                 \
        " mbarrier.try_wait.parity.acquire.cta.shared::cta.b64 p, [%1], %2;\n"         \
        " selp.b32 %0, 1, 0, p;\n}"                                                    \
        : "=r"(_done) : "r"(_mb), "r"(_ph) : "memory");                                \
    if (!_done) {                                                                      \
        asm volatile("{\n .reg .pred P1;\n"                                            \
            "WL_%=:\n"                                                                 \
            " mbarrier.try_wait.parity.acquire.cta.shared::cta.b64 P1, [%0], %1, 0x989680;\n" \
            " @P1 bra.uni WD_%=;\n bra.uni WL_%=;\nWD_%=:\n}"                          \
            :: "r"(_mb), "r"(_ph) : "memory");                                         \
    }                                                                                  \
} while (0)

// ----------------------------- GEMM (BM=256) --------------------------------
// C[M,N] = A @ B^T, tiled-swizzled bf16 operands.
// BM=256, BN=128, BK=64. 512 threads, 16 warps 4x4, warp tile 64x32.
// TERMS==3: fat chunks {A hi,lo}x2 + {B hi,lo} (96KB), 3 passes, 2 stages.
// TERMS==1: plain bf16, 48KB chunks, 4 stages.
// EPI: 0 = fp32 C store; 1 = encoder tanh+bias+mean -> query/q3.
#define SMEM_BYTES (1024 + 196608)

template <int EPI, int TERMS>
__global__ void __launch_bounds__(512, 1)
k_gemm(const bf16* __restrict__ A, const bf16* __restrict__ B,
       int nkbA, int nkbB, int K,
       float* __restrict__ C, int Nst,
       const float* __restrict__ bias,
       float* __restrict__ qout, bf16* __restrict__ q3out)
{
    extern __shared__ char smem[];
    const uint32_t sb = s2u(smem);
    const int tid = threadIdx.x, wid = tid >> 5, lane = tid & 31;
    const int wr = wid >> 2, wc = wid & 3;
    const int m0 = blockIdx.y * 256, n0 = blockIdx.x * 128;
    const int Kb = K / 64;
    const int rbA0 = blockIdx.y * 2;
    const int nb = blockIdx.x;

    if (tid == 0) {
#pragma unroll
        for (int s = 0; s < 4; s++) MBARRIER_INIT(sb + s * 8, 1);
    }
    __syncthreads();

    const uint32_t aTileSel = (wr >= 2) ? (uint32_t)TILE_B : 0u;
    uint32_t alin[4], blin[4];
#pragma unroll
    for (int mi = 0; mi < 4; mi++)
        alin[mi] = (uint32_t)(((wr & 1) * 64) + mi * 16 + (lane & 15)) * 128u + (uint32_t)(lane >> 4) * 16u;
#pragma unroll
    for (int ni = 0; ni < 4; ni++)
        blin[ni] = (uint32_t)(wc * 32 + ni * 8 + (lane & 7)) * 128u + (uint32_t)((lane >> 3) & 1) * 16u;

    float acc[4][4][4];
#pragma unroll
    for (int a = 0; a < 4; a++)
#pragma unroll
        for (int b = 0; b < 4; b++)
#pragma unroll
            for (int c = 0; c < 4; c++) acc[a][b][c] = 0.f;

    if (TERMS == 3) {
        const int NC = Kb;
        if (tid == 0) {
#pragma unroll
            for (int c0 = 0; c0 < 2; c0++) {
                if (c0 >= NC) break;
                uint32_t mb = sb + (uint32_t)c0 * 8;
                uint32_t dst = sb + 1024u + (uint32_t)c0 * 98304u;
                MBAR_ARRIVE_EXPECT(mb, 98304u);
                BULK_G2S(dst,           A + ((size_t)rbA0 * nkbA + c0) * TILE_E, TILE_B, mb);
                BULK_G2S(dst + 16384u,  A + ((size_t)(rbA0 + 1) * nkbA + c0) * TILE_E, TILE_B, mb);
                BULK_G2S(dst + 32768u,  A + ((size_t)rbA0 * nkbA + c0 + Kb) * TILE_E, TILE_B, mb);
                BULK_G2S(dst + 49152u,  A + ((size_t)(rbA0 + 1) * nkbA + c0 + Kb) * TILE_E, TILE_B, mb);
                BULK_G2S(dst + 65536u,  B + ((size_t)nb * nkbB + c0) * TILE_E, TILE_B, mb);
                BULK_G2S(dst + 81920u,  B + ((size_t)nb * nkbB + c0 + Kb) * TILE_E, TILE_B, mb);
            }
        }
        for (int c = 0; c < NC; c++) {
            int s = c & 1;
            MBARRIER_WAIT_PARITY(sb + s * 8, (c >> 1) & 1);
            const uint32_t stg = sb + 1024u + (uint32_t)s * 98304u;
            const uint32_t Ah = stg + aTileSel;
            const uint32_t Al = stg + 32768u + aTileSel;
            const uint32_t Bh = stg + 65536u;
            const uint32_t Bl = stg + 81920u;
#pragma unroll
            for (int ks = 0; ks < 4; ks++) {
                uint32_t af[4][4], bh[4][2], bl[4][2];
#pragma unroll
                for (int mi = 0; mi < 4; mi++) ldsm4(af[mi], Ah + swz(alin[mi] + ks * 32u));
#pragma unroll
                for (int ni = 0; ni < 4; ni++) ldsm2(bh[ni], Bh + swz(blin[ni] + ks * 32u));
#pragma unroll
                for (int ni = 0; ni < 4; ni++) ldsm2(bl[ni], Bl + swz(blin[ni] + ks * 32u));
#pragma unroll
                for (int mi = 0; mi < 4; mi++)
#pragma unroll
                    for (int ni = 0; ni < 4; ni++) mma16816(acc[mi][ni], af[mi], bh[ni]);
#pragma unroll
                for (int mi = 0; mi < 4; mi++)
#pragma unroll
                    for (int ni = 0; ni < 4; ni++) mma16816(acc[mi][ni], af[mi], bl[ni]);
#pragma unroll
                for (int mi = 0; mi < 4; mi++) ldsm4(af[mi], Al + swz(alin[mi] + ks * 32u));
#pragma unroll
                for (int mi = 0; mi < 4; mi++)
#pragma unroll
                    for (int ni = 0; ni < 4; ni++) mma16816(acc[mi][ni], af[mi], bh[ni]);
            }
            __syncthreads();
            if (c + 2 < NC && tid == 0) {
                int cn = c + 2;
                uint32_t mb = sb + (uint32_t)s * 8;
                uint32_t dst = sb + 1024u + (uint32_t)s * 98304u;
                MBAR_ARRIVE_EXPECT(mb, 98304u);
                BULK_G2S(dst,           A + ((size_t)rbA0 * nkbA + cn) * TILE_E, TILE_B, mb);
                BULK_G2S(dst + 16384u,  A + ((size_t)(rbA0 + 1) * nkbA + cn) * TILE_E, TILE_B, mb);
                BULK_G2S(dst + 32768u,  A + ((size_t)rbA0 * nkbA + cn + Kb) * TILE_E, TILE_B, mb);
                BULK_G2S(dst + 49152u,  A + ((size_t)(rbA0 + 1) * nkbA + cn + Kb) * TILE_E, TILE_B, mb);
                BULK_G2S(dst + 65536u,  B + ((size_t)nb * nkbB + cn) * TILE_E, TILE_B, mb);
                BULK_G2S(dst + 81920u,  B + ((size_t)nb * nkbB + cn + Kb) * TILE_E, TILE_B, mb);
            }
        }
    } else {
        const int NC = Kb;
        if (tid == 0) {
#pragma unroll
            for (int c0 = 0; c0 < 3; c0++) {
                if (c0 >= NC) break;
                uint32_t mb = sb + (uint32_t)c0 * 8;
                uint32_t dst = sb + 1024u + (uint32_t)c0 * 49152u;
                MBAR_ARRIVE_EXPECT(mb, 49152u);
                BULK_G2S(dst,              A + ((size_t)rbA0 * nkbA + c0) * TILE_E, TILE_B, mb);
                BULK_G2S(dst + TILE_B,     A + ((size_t)(rbA0 + 1) * nkbA + c0) * TILE_E, TILE_B, mb);
                BULK_G2S(dst + 2 * TILE_B, B + ((size_t)nb * nkbB + c0) * TILE_E, TILE_B, mb);
            }
        }
        for (int c = 0; c < NC; c++) {
            int s = c & 3;
            MBARRIER_WAIT_PARITY(sb + s * 8, (c >> 2) & 1);
            const uint32_t As = sb + 1024u + (uint32_t)s * 49152u + aTileSel;
            const uint32_t Bs = sb + 1024u + (uint32_t)s * 49152u + 2u * TILE_B;
#pragma unroll
            for (int ks = 0; ks < 4; ks++) {
                uint32_t af[4][4], bfr[4][2];
#pragma unroll
                for (int mi = 0; mi < 4; mi++) ldsm4(af[mi], As + swz(alin[mi] + ks * 32u));
#pragma unroll
                for (int ni = 0; ni < 4; ni++) ldsm2(bfr[ni], Bs + swz(blin[ni] + ks * 32u));
#pragma unroll
                for (int mi = 0; mi < 4; mi++)
#pragma unroll
                    for (int ni = 0; ni < 4; ni++) mma16816(acc[mi][ni], af[mi], bfr[ni]);
            }
            __syncthreads();
            if (c + 3 < NC && tid == 0) {
                int cn = c + 3;
                int sn = cn & 3;
                uint32_t mb = sb + (uint32_t)sn * 8;
                uint32_t dst = sb + 1024u + (uint32_t)sn * 49152u;
                MBAR_ARRIVE_EXPECT(mb, 49152u);
                BULK_G2S(dst,              A + ((size_t)rbA0 * nkbA + cn) * TILE_E, TILE_B, mb);
                BULK_G2S(dst + TILE_B,     A + ((size_t)(rbA0 + 1) * nkbA + cn) * TILE_E, TILE_B, mb);
                BULK_G2S(dst + 2 * TILE_B, B + ((size_t)nb * nkbB + cn) * TILE_E, TILE_B, mb);
            }
        }
    }

    if (EPI == 0) {
#pragma unroll
        for (int mi = 0; mi < 4; mi++) {
            int r = m0 + wr * 64 + mi * 16 + (lane >> 2);
#pragma unroll
            for (int ni = 0; ni < 4; ni++) {
                int col = n0 + wc * 32 + ni * 8 + 2 * (lane & 3);
                *(float2*)&C[(size_t)r * Nst + col] = make_float2(acc[mi][ni][0], acc[mi][ni][1]);
                *(float2*)&C[(size_t)(r + 8) * Nst + col] = make_float2(acc[mi][ni][2], acc[mi][ni][3]);
            }
        }
    } else {
        // rows = batch*SEQ; 32-row group = one batch; warp holds 2 batches.
#pragma unroll
        for (int b = 0; b < 2; b++) {
            int batch = m0 / 32 + wr * 2 + b;
#pragma unroll
            for (int ni = 0; ni < 4; ni++) {
                int col0 = n0 + wc * 32 + ni * 8 + 2 * (lane & 3);
                float bi0 = bias[col0], bi1 = bias[col0 + 1];
                float s0 = 0.f, s1 = 0.f;
#pragma unroll
                for (int mh = 0; mh < 2; mh++) {
                    float* cc = acc[b * 2 + mh][ni];
                    s0 += fast_tanh(cc[0] + bi0) + fast_tanh(cc[2] + bi0);
                    s1 += fast_tanh(cc[1] + bi1) + fast_tanh(cc[3] + bi1);
                }
#pragma unroll
                for (int o = 4; o <= 16; o <<= 1) {
                    s0 += __shfl_xor_sync(0xffffffffu, s0, o);
                    s1 += __shfl_xor_sync(0xffffffffu, s1, o);
                }
                if (lane < 4) {
                    float q0 = s0 * (1.0f / SEQ), q1 = s1 * (1.0f / SEQ);
                    qout[(size_t)batch * HID + col0] = q0;
                    qout[(size_t)batch * HID + col0 + 1] = q1;
                    uint32_t lin = swz(((uint32_t)(batch & 127) << 7) + ((uint32_t)(col0 & 63) << 1));
                    int rb = batch >> 7, kb = col0 >> 6;
                    char* th = (char*)q3out + ((size_t)rb * (2 * HID / 64) + kb) * TILE_B + lin;
                    char* tl = (char*)q3out + ((size_t)rb * (2 * HID / 64) + kb + HID / 64) * TILE_B + lin;
                    bf16 h0 = __float2bfloat16(q0), h1 = __float2bfloat16(q1);
                    *(uint32_t*)th = pk2(q0, q1);
                    *(uint32_t*)tl = pk2(q0 - __bfloat162float(h0), q1 - __bfloat162float(h1));
                }
            }
        }
    }
}

// ------------------- GEMM (BM=128, TERMS=3, for decoder) --------------------
// 256 threads, 8 warps 2x4, warp tile 64x32. Stage = {A hi, A lo, B hi, B lo}
// = 64KB, 3 stages. Per-element accumulation order identical to k_gemm<0,3>.
#define SMEM128 (1024 + 3 * 65536)

__global__ void __launch_bounds__(256, 1)
k_gemm128(const bf16* __restrict__ A, const bf16* __restrict__ B,
          int nkbA, int nkbB, int K,
          float* __restrict__ C, int Nst)
{
    extern __shared__ char smem[];
    const uint32_t sb = s2u(smem);
    const int tid = threadIdx.x, wid = tid >> 5, lane = tid & 31;
    const int wr = wid >> 2, wc = wid & 3;
    const int m0 = blockIdx.y * 128, n0 = blockIdx.x * 128;
    const int Kb = K / 64;
    const int rbA = blockIdx.y;
    const int nb = blockIdx.x;

    if (tid == 0) {
#pragma unroll
        for (int s = 0; s < 3; s++) MBARRIER_INIT(sb + s * 8, 1);
    }
    __syncthreads();

    uint32_t alin[4], blin[4];
#pragma unroll
    for (int mi = 0; mi < 4; mi++)
        alin[mi] = (uint32_t)(wr * 64 + mi * 16 + (lane & 15)) * 128u + (uint32_t)(lane >> 4) * 16u;
#pragma unroll
    for (int ni = 0; ni < 4; ni++)
        blin[ni] = (uint32_t)(wc * 32 + ni * 8 + (lane & 7)) * 128u + (uint32_t)((lane >> 3) & 1) * 16u;

    float acc[4][4][4];
#pragma unroll
    for (int a = 0; a < 4; a++)
#pragma unroll
        for (int b = 0; b < 4; b++)
#pragma unroll
            for (int c = 0; c < 4; c++) acc[a][b][c] = 0.f;

    const int NC = Kb;
    if (tid == 0) {
#pragma unroll
        for (int c0 = 0; c0 < 2; c0++) {
            if (c0 >= NC) break;
            uint32_t mb = sb + (uint32_t)c0 * 8;
            uint32_t dst = sb + 1024u + (uint32_t)c0 * 65536u;
            MBAR_ARRIVE_EXPECT(mb, 65536u);
            BULK_G2S(dst,           A + ((size_t)rbA * nkbA + c0) * TILE_E, TILE_B, mb);
            BULK_G2S(dst + 16384u,  A + ((size_t)rbA * nkbA + c0 + Kb) * TILE_E, TILE_B, mb);
            BULK_G2S(dst + 32768u,  B + ((size_t)nb * nkbB + c0) * TILE_E, TILE_B, mb);
            BULK_G2S(dst + 49152u,  B + ((size_t)nb * nkbB + c0 + Kb) * TILE_E, TILE_B, mb);
        }
    }
    for (int c = 0; c < NC; c++) {
        int s = c % 3;
        MBARRIER_WAIT_PARITY(sb + s * 8, (c / 3) & 1);
        const uint32_t stg = sb + 1024u + (uint32_t)s * 65536u;
        const uint32_t Ah = stg;
        const uint32_t Al = stg + 16384u;
        const uint32_t Bh = stg + 32768u;
        const uint32_t Bl = stg + 49152u;
#pragma unroll
        for (int ks = 0; ks < 4; ks++) {
            uint32_t af[4][4], bh[4][2], bl[4][2];
#pragma unroll
            for (int mi = 0; mi < 4; mi++) ldsm4(af[mi], Ah + swz(alin[mi] + ks * 32u));
#pragma unroll
            for (int ni = 0; ni < 4; ni++) ldsm2(bh[ni], Bh + swz(blin[ni] + ks * 32u));
#pragma unroll
            for (int ni = 0; ni < 4; ni++) ldsm2(bl[ni], Bl + swz(blin[ni] + ks * 32u));
#pragma unroll
            for (int mi = 0; mi < 4; mi++)
#pragma unroll
                for (int ni = 0; ni < 4; ni++) mma16816(acc[mi][ni], af[mi], bh[ni]);
#pragma unroll
            for (int mi = 0; mi < 4; mi++)
#pragma unroll
                for (int ni = 0; ni < 4; ni++) mma16816(acc[mi][ni], af[mi], bl[ni]);
#pragma unroll
            for (int mi = 0; mi < 4; mi++) ldsm4(af[mi], Al + swz(alin[mi] + ks * 32u));
#pragma unroll
            for (int mi = 0; mi < 4; mi++)
#pragma unroll
                for (int ni = 0; ni < 4; ni++) mma16816(acc[mi][ni], af[mi], bh[ni]);
        }
        __syncthreads();
        if (c + 2 < NC && tid == 0) {
            int cn = c + 2;
            int sn = cn % 3;
            uint32_t mb = sb + (uint32_t)sn * 8;
            uint32_t dst = sb + 1024u + (uint32_t)sn * 65536u;
            MBAR_ARRIVE_EXPECT(mb, 65536u);
            BULK_G2S(dst,           A + ((size_t)rbA * nkbA + cn) * TILE_E, TILE_B, mb);
            BULK_G2S(dst + 16384u,  A + ((size_t)rbA * nkbA + cn + Kb) * TILE_E, TILE_B, mb);
            BULK_G2S(dst + 32768u,  B + ((size_t)nb * nkbB + cn) * TILE_E, TILE_B, mb);
            BULK_G2S(dst + 49152u,  B + ((size_t)nb * nkbB + cn + Kb) * TILE_E, TILE_B, mb);
        }
    }

#pragma unroll
    for (int mi = 0; mi < 4; mi++) {
        int r = m0 + wr * 64 + mi * 16 + (lane >> 2);
#pragma unroll
        for (int ni = 0; ni < 4; ni++) {
            int col = n0 + wc * 32 + ni * 8 + 2 * (lane & 3);
            *(float2*)&C[(size_t)r * Nst + col] = make_float2(acc[mi][ni][0], acc[mi][ni][1]);
            *(float2*)&C[(size_t)(r + 8) * Nst + col] = make_float2(acc[mi][ni][2], acc[mi][ni][3]);
        }
    }
}

// ---------------------- prep: row-major fp32 -> tiled hi|lo ----------------
__global__ void k_dec_t(const float* __restrict__ in, bf16* __restrict__ out,
                        int K, long nGran)
{
    long g = (long)blockIdx.x * 256 + threadIdx.x;
    if (g >= nGran) return;
    int perRow = K / 8;
    long r = g / perRow;
    int c = (int)(g % perRow) * 8;
    float4 v0 = *(const float4*)(in + r * K + c);
    float4 v1 = *(const float4*)(in + r * K + c + 4);
    float f[8] = {v0.x, v0.y, v0.z, v0.w, v1.x, v1.y, v1.z, v1.w};
    uint32_t hi[4], lo[4];
#pragma unroll
    for (int j = 0; j < 4; j++) {
        bf16 h0 = __float2bfloat16(f[2 * j]), h1 = __float2bfloat16(f[2 * j + 1]);
        __nv_bfloat162 hp; hp.x = h0; hp.y = h1;
        hi[j] = *(uint32_t*)&hp;
        lo[j] = pk2(f[2 * j] - __bfloat162float(h0), f[2 * j + 1] - __bfloat162float(h1));
    }
    int rb = (int)(r >> 7), kb = c >> 6, kbT = 2 * K / 64;
    uint32_t lin = swz(((uint32_t)(r & 127) << 7) + ((uint32_t)(c & 63) << 1));
    *(uint4*)((char*)out + ((size_t)rb * kbT + kb) * TILE_B + lin) = make_uint4(hi[0], hi[1], hi[2], hi[3]);
    *(uint4*)((char*)out + ((size_t)rb * kbT + kb + K / 64) * TILE_B + lin) = make_uint4(lo[0], lo[1], lo[2], lo[3]);
}

// ------------- prep: transpose fp32 [K][N] -> tiled rows=n ------------------
template <bool LO>
__global__ void k_tdec_t(const float* __restrict__ in, bf16* __restrict__ out,
                         int K, int N)
{
    __shared__ float tile[32][33];
    int n0 = blockIdx.x * 32, k0 = blockIdx.y * 32;
    int tx = threadIdx.x & 31, ty = threadIdx.x >> 5;
    for (int r = ty; r < 32; r += 8)
        tile[r][tx] = in[(size_t)(k0 + r) * N + n0 + tx];
    __syncthreads();
    int t = threadIdx.x;
    if (t < 128) {
        int nl = t & 31, kg = t >> 5;
        float f[8];
#pragma unroll
        for (int j = 0; j < 8; j++) f[j] = tile[kg * 8 + j][nl];
        int n = n0 + nl, k = k0 + kg * 8;
        uint32_t hi[4], lo[4];
#pragma unroll
        for (int j = 0; j < 4; j++) {
            bf16 h0 = __float2bfloat16(f[2 * j]), h1 = __float2bfloat16(f[2 * j + 1]);
            __nv_bfloat162 hp; hp.x = h0; hp.y = h1;
            hi[j] = *(uint32_t*)&hp;
            if (LO)
                lo[j] = pk2(f[2 * j] - __bfloat162float(h0), f[2 * j + 1] - __bfloat162float(h1));
        }
        int rb = n >> 7, kb = k >> 6;
        int kbT = LO ? 2 * K / 64 : K / 64;
        uint32_t lin = swz(((uint32_t)(n & 127) << 7) + ((uint32_t)(k & 63) << 1));
        *(uint4*)((char*)out + ((size_t)rb * kbT + kb) * TILE_B + lin) = make_uint4(hi[0], hi[1], hi[2], hi[3]);
        if (LO)
            *(uint4*)((char*)out + ((size_t)rb * kbT + kb + K / 64) * TILE_B + lin) = make_uint4(lo[0], lo[1], lo[2], lo[3]);
    }
}

// ---- fused: gate + top-k + softmax over one sim row (block = one batch) ----
__global__ void k_simfuse(const float* __restrict__ sim,
                          const float* __restrict__ query,
                          const float* __restrict__ w_curv,
                          const float* __restrict__ b_curv,
                          const float* __restrict__ temperature,
                          bf16* __restrict__ out)
{
    __shared__ float sv[MS];
    __shared__ float red[256];
    __shared__ float cv[256];
    __shared__ int   ci[256];
    __shared__ float s_scale;

    int b = blockIdx.x, tid = threadIdx.x;
    int w = tid >> 5, lane = tid & 31;

    const float* row = sim + (size_t)b * MS;
    float mx = -FLT_MAX;
    for (int i = tid; i < MS; i += 256) { float v = row[i]; sv[i] = v; mx = fmaxf(mx, v); }

    float gs = 0.f;
    for (int h = tid; h < HID; h += 256)
        gs += query[(size_t)b * HID + h] * w_curv[h];
    red[tid] = gs; __syncthreads();
    for (int off = 128; off; off >>= 1) { if (tid < off) red[tid] += red[tid + off]; __syncthreads(); }
    if (tid == 0) {
        float gate = 1.0f / (1.0f + expf(-(red[0] + b_curv[0])));
        s_scale = (0.5f + gate) / fmaxf(temperature[0], 1e-6f);
    }
    __syncthreads();
    float scale = s_scale;

    red[tid] = mx; __syncthreads();
    for (int off = 128; off; off >>= 1) { if (tid < off) red[tid] = fmaxf(red[tid], red[tid + off]); __syncthreads(); }
    mx = red[0]; __syncthreads();

    float v[16];
#pragma unroll
    for (int j = 0; j < 16; j++) v[j] = sv[w * 512 + j * 32 + lane] * scale;

    for (int it = 0; it < NK; it++) {
        float bv = -FLT_MAX; int bj = 0;
#pragma unroll
        for (int j = 0; j < 16; j++)
            if (v[j] > bv) { bv = v[j]; bj = j; }
        int bi = w * 512 + bj * 32 + lane;
#pragma unroll
        for (int o = 16; o; o >>= 1) {
            float ov = __shfl_xor_sync(0xffffffffu, bv, o);
            int   oi = __shfl_xor_sync(0xffffffffu, bi, o);
            if (ov > bv || (ov == bv && oi < bi)) { bv = ov; bi = oi; }
        }
        if ((bi & 31) == lane) v[(bi >> 5) & 15] = -FLT_MAX;
        if (lane == 0) { cv[w * 32 + it] = bv; ci[w * 32 + it] = bi; }
    }
    __syncthreads();

    if (w == 0) {
        float pv[8]; int pi[8];
#pragma unroll
        for (int j = 0; j < 8; j++) { pv[j] = cv[lane + j * 32]; pi[j] = ci[lane + j * 32]; }
        for (int k = 0; k < NK; k++) {
            float bv = -FLT_MAX; int bi = 0x7FFFFFFF;
#pragma unroll
            for (int j = 0; j < 8; j++)
                if (pv[j] > bv || (pv[j] == bv && pi[j] < bi)) { bv = pv[j]; bi = pi[j]; }
#pragma unroll
            for (int o = 16; o; o >>= 1) {
                float ov = __shfl_xor_sync(0xffffffffu, bv, o);
                int   oi = __shfl_xor_sync(0xffffffffu, bi, o);
                if (ov > bv || (ov == bv && oi < bi)) { bv = ov; bi = oi; }
            }
#pragma unroll
            for (int j = 0; j < 8; j++)
                if (pi[j] == bi) pv[j] = -FLT_MAX;
            if (lane == 0) {
                g_vals[(size_t)b * NK + k] = bv;
                g_idx [(size_t)b * NK + k] = bi;
            }
        }
    }
    __syncthreads();

    float s = 0.f;
    for (int i = tid; i < MS; i += 256) { float e = expf(sv[i] - mx); sv[i] = e; s += e; }
    red[tid] = s; __syncthreads();
    for (int off = 128; off; off >>= 1) { if (tid < off) red[tid] += red[tid + off]; __syncthreads(); }
    float inv = 1.0f / red[0];
    int rb = b >> 7;
    uint32_t rlin = (uint32_t)(b & 127) << 7;
    for (int gI = tid; gI < MS / 8; gI += 256) {
        int c = gI * 8;
        uint32_t hi[4];
#pragma unroll
        for (int j = 0; j < 4; j++)
            hi[j] = pk2(sv[c + 2 * j] * inv, sv[c + 2 * j + 1] * inv);
        uint32_t lin = swz(rlin + ((uint32_t)(c & 63) << 1));
        *(uint4*)((char*)out + ((size_t)rb * (MS / 64) + (c >> 6)) * TILE_B + lin)
            = make_uint4(hi[0], hi[1], hi[2], hi[3]);
    }
}

// ------------- softmax over M=4096 -> tiled bf16 (hi only) ------------------
__global__ void k_softmax_dec(const float* __restrict__ in, bf16* __restrict__ out)
{
    __shared__ float sv[MS];
    __shared__ float red[256];
    int b = blockIdx.x, tid = threadIdx.x;
    const float* row = in + (size_t)b * MS;
    float mx = -FLT_MAX;
    for (int i = tid; i < MS; i += 256) { float v = row[i]; sv[i] = v; mx = fmaxf(mx, v); }
    red[tid] = mx; __syncthreads();
    for (int off = 128; off; off >>= 1) { if (tid < off) red[tid] = fmaxf(red[tid], red[tid + off]); __syncthreads(); }
    mx = red[0]; __syncthreads();
    float s = 0.f;
    for (int i = tid; i < MS; i += 256) { float e = expf(sv[i] - mx); sv[i] = e; s += e; }
    red[tid] = s; __syncthreads();
    for (int off = 128; off; off >>= 1) { if (tid < off) red[tid] += red[tid + off]; __syncthreads(); }
    float inv = 1.0f / red[0];
    int rb = b >> 7;
    uint32_t rlin = (uint32_t)(b & 127) << 7;
    for (int gI = tid; gI < MS / 8; gI += 256) {
        int c = gI * 8;
        uint32_t hi[4];
#pragma unroll
        for (int j = 0; j < 4; j++)
            hi[j] = pk2(sv[c + 2 * j] * inv, sv[c + 2 * j + 1] * inv);
        uint32_t lin = swz(rlin + ((uint32_t)(c & 63) << 1));
        *(uint4*)((char*)out + ((size_t)rb * (MS / 64) + (c >> 6)) * TILE_B + lin)
            = make_uint4(hi[0], hi[1], hi[2], hi[3]);
    }
}

// ------- combine: softmax(vals + act[idx]); read3 (tiled hi|lo) -------------
__global__ void k_combine(const float* __restrict__ act,
                          const float* __restrict__ mem)
{
    __shared__ float comb[NK];
    __shared__ int   sidx[NK];
    int b = blockIdx.x, tid = threadIdx.x;
    if (tid < NK) {
        int id = g_idx[(size_t)b * NK + tid];
        sidx[tid] = id;
        float t = g_vals[(size_t)b * NK + tid] + act[(size_t)b * MS + id];
        float m = t;
#pragma unroll
        for (int o = 16; o; o >>= 1) m = fmaxf(m, __shfl_xor_sync(0xffffffffu, m, o));
        float e = expf(t - m);
        float s = e;
#pragma unroll
        for (int o = 16; o; o >>= 1) s += __shfl_xor_sync(0xffffffffu, s, o);
        comb[tid] = e / s;
    }
    __syncthreads();
    int rb = b >> 7;
    uint32_t rlin = (uint32_t)(b & 127) << 7;
    if (tid < HID / 8) {
        int h0 = tid * 8;
        float a[8] = {0, 0, 0, 0, 0, 0, 0, 0};
#pragma unroll
        for (int k = 0; k < NK; k++) {
            float cb = comb[k];
            const float4* mr = (const float4*)(mem + (size_t)sidx[k] * HID + h0);
            float4 m0 = mr[0], m1 = mr[1];
            a[0] += cb * m0.x; a[1] += cb * m0.y; a[2] += cb * m0.z; a[3] += cb * m0.w;
            a[4] += cb * m1.x; a[5] += cb * m1.y; a[6] += cb * m1.z; a[7] += cb * m1.w;
        }
        uint32_t hi[4], lo[4];
#pragma unroll
        for (int j = 0; j < 4; j++) {
            bf16 h0b = __float2bfloat16(a[2 * j]), h1b = __float2bfloat16(a[2 * j + 1]);
            __nv_bfloat162 hp; hp.x = h0b; hp.y = h1b;
            hi[j] = *(uint32_t*)&hp;
            lo[j] = pk2(a[2 * j] - __bfloat162float(h0b), a[2 * j + 1] - __bfloat162float(h1b));
        }
        int kb = h0 >> 6;
        uint32_t lin = swz(rlin + ((uint32_t)(h0 & 63) << 1));
        *(uint4*)((char*)g_read3 + ((size_t)rb * (2 * HID / 64) + kb) * TILE_B + lin)
            = make_uint4(hi[0], hi[1], hi[2], hi[3]);
        *(uint4*)((char*)g_read3 + ((size_t)rb * (2 * HID / 64) + kb + HID / 64) * TILE_B + lin)
            = make_uint4(lo[0], lo[1], lo[2], lo[3]);
    }
}

// --------------- broadcast: out[b,s,:] = tanh(orow + b_dec) ----------------
__global__ void k_broadcast(const float* __restrict__ orow,
                            const float* __restrict__ bdec,
                            float* __restrict__ out)
{
    int t = blockIdx.x * blockDim.x + threadIdx.x;
    if (t < BATCH * DIM / 4) {
        int b = t / (DIM / 4), dq = t % (DIM / 4);
        float4 v = ((const float4*)orow)[(size_t)b * (DIM / 4) + dq];
        float4 bb = ((const float4*)bdec)[dq];
        v.x = tanhf(v.x + bb.x); v.y = tanhf(v.y + bb.y);
        v.z = tanhf(v.z + bb.z); v.w = tanhf(v.w + bb.w);
        float4* o = (float4*)out;
#pragma unroll
        for (int s = 0; s < SEQ; s++)
            o[((size_t)b * SEQ + s) * (DIM / 4) + dq] = v;
    }
}

// ---------------------------------------------------------------------------
extern "C" void kernel_launch(void* const* d_in, const int* in_sizes, int n_in,
                              void* d_out, int out_size)
{
    int i = 1;
    if (in_sizes[1] < 16) i = 2;   // skip scalar 'topk' input if present

    const float* x      = (const float*)d_in[0];
    const float* W_enc  = (const float*)d_in[i++];
    const float* b_enc  = (const float*)d_in[i++];
    const float* w_curv = (const float*)d_in[i++];
    const float* b_curv = (const float*)d_in[i++];
    const float* mem    = (const float*)d_in[i++];
    const float* assoc  = (const float*)d_in[i++];
    const float* W_dec  = (const float*)d_in[i++];
    const float* b_dec  = (const float*)d_in[i++];
    const float* temp   = (const float*)d_in[i++];
    float* out = (float*)d_out;

    bf16 *x3, *We3, *mem3, *as1, *Wd3, *q3, *act1, *read3;
    float *query, *sim, *actB, *orow;
    cudaGetSymbolAddress((void**)&x3,    g_x3);
    cudaGetSymbolAddress((void**)&We3,   g_We3);
    cudaGetSymbolAddress((void**)&mem3,  g_mem3);
    cudaGetSymbolAddress((void**)&as1,   g_as);
    cudaGetSymbolAddress((void**)&Wd3,   g_Wd3);
    cudaGetSymbolAddress((void**)&q3,    g_q3);
    cudaGetSymbolAddress((void**)&act1,  g_act);
    cudaGetSymbolAddress((void**)&read3, g_read3);
    cudaGetSymbolAddress((void**)&query, g_query);
    cudaGetSymbolAddress((void**)&sim,   g_sim);
    cudaGetSymbolAddress((void**)&actB,  g_actB);
    cudaGetSymbolAddress((void**)&orow,  g_orow);

    cudaFuncSetAttribute(k_gemm<0, 3>, cudaFuncAttributeMaxDynamicSharedMemorySize, SMEM_BYTES);
    cudaFuncSetAttribute(k_gemm<1, 3>, cudaFuncAttributeMaxDynamicSharedMemorySize, SMEM_BYTES);
    cudaFuncSetAttribute(k_gemm<0, 1>, cudaFuncAttributeMaxDynamicSharedMemorySize, SMEM_BYTES);
    cudaFuncSetAttribute(k_gemm128, cudaFuncAttributeMaxDynamicSharedMemorySize, SMEM128);

    // side stream + fork/join events (created once, on the un-captured
    // correctness call; only record/wait ops execute during graph capture)
    static cudaStream_t s1 = nullptr;
    static cudaEvent_t evFork = nullptr, evJoin = nullptr;
    if (s1 == nullptr) {
        cudaStreamCreateWithFlags(&s1, cudaStreamNonBlocking);
        cudaEventCreateWithFlags(&evFork, cudaEventDisableTiming);
        cudaEventCreateWithFlags(&evJoin, cudaEventDisableTiming);
    }

    // ---- fork: weight preps on s1, x decomposition (DRAM hog) on main ----
    cudaEventRecord(evFork, 0);
    cudaStreamWaitEvent(s1, evFork, 0);
    k_tdec_t<true><<<dim3(HID / 32, DIM / 32), 256, 0, s1>>>(W_enc, We3, DIM, HID);
    k_dec_t<<<(int)(((long)MS * HID / 8 + 255) / 256), 256, 0, s1>>>(
        mem, mem3, HID, (long)MS * HID / 8);
    k_tdec_t<false><<<dim3(MS / 32, MS / 32), 256, 0, s1>>>(assoc, as1, MS, MS);
    k_tdec_t<true><<<dim3(DIM / 32, HID / 32), 256, 0, s1>>>(W_dec, Wd3, HID, DIM);
    cudaEventRecord(evJoin, s1);

    k_dec_t<<<(int)(((long)BATCH * SEQ * DIM / 8 + 255) / 256), 256>>>(
        x, x3, DIM, (long)BATCH * SEQ * DIM / 8);
    cudaStreamWaitEvent(0, evJoin, 0);   // join before encoder

    // ---- encoder GEMM (bf16x3 fat) + fused tanh/bias/mean ----
    k_gemm<1, 3><<<dim3(HID / 128, BATCH * SEQ / 256), 512, SMEM_BYTES>>>(
        x3, We3, 2 * DIM / 64, 2 * DIM / 64, DIM, nullptr, 0, b_enc, query, q3);
    // ---- sim = query @ mem^T ----
    k_gemm<0, 3><<<dim3(MS / 128, BATCH / 256), 512, SMEM_BYTES>>>(
        q3, mem3, 2 * HID / 64, 2 * HID / 64, HID, sim, MS, nullptr, nullptr, nullptr);
    // ---- fused gate + top-k + softmax #1 ----
    k_simfuse<<<BATCH, 256>>>(sim, query, w_curv, b_curv, temp, act1);
    // ---- assoc GEMM #1 ----
    k_gemm<0, 1><<<dim3(MS / 128, BATCH / 256), 512, SMEM_BYTES>>>(
        act1, as1, MS / 64, MS / 64, MS, actB, MS, nullptr, nullptr, nullptr);
    // ---- softmax #2 -> assoc GEMM #2 ----
    k_softmax_dec<<<BATCH, 256>>>(actB, act1);
    k_gemm<0, 1><<<dim3(MS / 128, BATCH / 256), 512, SMEM_BYTES>>>(
        act1, as1, MS / 64, MS / 64, MS, actB, MS, nullptr, nullptr, nullptr);
    // ---- combine + gather-read ----
    k_combine<<<BATCH, 256>>>(actB, mem);
    // ---- decoder GEMM (BM=128: 128 CTAs, 86% chip) -> orow ----
    k_gemm128<<<dim3(DIM / 128, BATCH / 128), 256, SMEM128>>>(
        read3, Wd3, 2 * HID / 64, 2 * HID / 64, HID, orow, DIM);
    // ---- bias + tanh + broadcast over S ----
    k_broadcast<<<(BATCH * DIM / 4 + 255) / 256, 256>>>(orow, b_dec, out);
}